// round 9
// baseline (speedup 1.0000x reference)
#include <cuda_runtime.h>
#include <cuda_bf16.h>
#include <cstdint>

// ---------------------------------------------------------------------------
// Sparse submanifold 3D conv backbone, batch=1, 128^3 -> 2^3.
// L0 conv1+conv2 (density 4.8%): neighbor-skipping scalar fp32 kernels.
// L1..L3: mma.sync bf16x3 split-fp32, 3-stage cp.async pipeline + id prefetch.
// Levels 4-6 (n <= 512): scalar FFMA path.
// ---------------------------------------------------------------------------

#define NMAX 100000
#define GRID_CELLS (1 << 21)
#define FLAGS_MAX (1 << 18)

__device__ int   g_n[8];
__device__ int   g_linA[NMAX];
__device__ int   g_linB[NMAX];
__device__ int   g_gridA[GRID_CELLS];
__device__ int   g_gridB[GRID_CELLS];
__device__ int   g_pairs[27 * NMAX];
__device__ int   g_flags[FLAGS_MAX];
__device__ int   g_bsums[256];
__device__ __align__(1024) float g_featA[10000000];
__device__ __align__(1024) float g_featB[10000000];
// bf16 hi/lo feature tables: pair-1 = conv1 input, pair-2 = conv2 input
__device__ __align__(1024) __nv_bfloat16 g_bh1[12000000];
__device__ __align__(1024) __nv_bfloat16 g_bl1[12000000];
__device__ __align__(1024) __nv_bfloat16 g_bh2[12000000];
__device__ __align__(1024) __nv_bfloat16 g_bl2[12000000];
// pre-swizzled, transposed, split weight blob (layers 2..7)
__device__ __align__(1024) unsigned char g_wblob[16 * 1024 * 1024];

// ---------------------------------------------------------------------------

__device__ __forceinline__ void cp_async16(uint32_t dst, const void* src, int srcBytes) {
    asm volatile("cp.async.cg.shared.global [%0], [%1], 16, %2;\n"
                 :: "r"(dst), "l"(src), "r"(srcBytes));
}
__device__ __forceinline__ void cp_commit() {
    asm volatile("cp.async.commit_group;\n");
}
__device__ __forceinline__ uint32_t smem_u32(const void* p) {
    uint32_t a;
    asm("{ .reg .u64 t; cvta.to.shared.u64 t, %1; cvt.u32.u64 %0, t; }" : "=r"(a) : "l"(p));
    return a;
}
__device__ __forceinline__ void ldsm4(uint32_t* r, uint32_t addr) {
    asm volatile("ldmatrix.sync.aligned.m8n8.x4.shared.b16 {%0,%1,%2,%3}, [%4];"
                 : "=r"(r[0]), "=r"(r[1]), "=r"(r[2]), "=r"(r[3]) : "r"(addr));
}
__device__ __forceinline__ void ldsm2(uint32_t* r, uint32_t addr) {
    asm volatile("ldmatrix.sync.aligned.m8n8.x2.shared.b16 {%0,%1}, [%2];"
                 : "=r"(r[0]), "=r"(r[1]) : "r"(addr));
}
__device__ __forceinline__ void mma16816(float* d, const uint32_t* a, const uint32_t* b) {
    asm volatile("mma.sync.aligned.m16n8k16.row.col.f32.bf16.bf16.f32 "
                 "{%0,%1,%2,%3}, {%4,%5,%6,%7}, {%8,%9}, {%0,%1,%2,%3};"
                 : "+f"(d[0]), "+f"(d[1]), "+f"(d[2]), "+f"(d[3])
                 : "r"(a[0]), "r"(a[1]), "r"(a[2]), "r"(a[3]), "r"(b[0]), "r"(b[1]));
}

// ---------------------------------------------------------------------------

__global__ void k_setn(int n0) { g_n[0] = n0; }

__global__ void k_fill(int* g, int v, int P) {
    int i = blockIdx.x * blockDim.x + threadIdx.x;
    if (i < P) g[i] = v;
}

__global__ void k_scatter0(const int* __restrict__ coors, int n0) {
    int i = blockIdx.x * blockDim.x + threadIdx.x;
    if (i >= n0) return;
    int z = coors[i * 4 + 1];
    int y = coors[i * 4 + 2];
    int x = coors[i * 4 + 3];
    int l = (z * 128 + y) * 128 + x;
    g_linA[i] = l;
    g_gridA[l] = i;
}

__global__ void k_pairs(const int* __restrict__ lin, const int* __restrict__ grid,
                        const int* __restrict__ np, int S) {
    int n = *np;
    int i = blockIdx.x * blockDim.x + threadIdx.x;
    if (i >= n) return;
    int l = lin[i];
    int z = l / (S * S);
    int rem = l - z * S * S;
    int y = rem / S;
    int x = rem - y * S;
    int k = 0;
    #pragma unroll
    for (int dz = -1; dz <= 1; dz++)
        #pragma unroll
        for (int dy = -1; dy <= 1; dy++)
            #pragma unroll
            for (int dx = -1; dx <= 1; dx++) {
                int zz = z + dz, yy = y + dy, xx = x + dx;
                int v = -1;
                if (zz >= 0 && zz < S && yy >= 0 && yy < S && xx >= 0 && xx < S)
                    v = grid[(zz * S + yy) * S + xx];
                g_pairs[k * NMAX + i] = v;
                k++;
            }
}

// Weight blob: W[27,Cin,Cout] fp32 -> per-stage SW128 images of W^T
// [Cout rows x 64 cols] bf16, hi then lo. Stage = (k, ci-chunk).
__global__ void k_wcvt(const float* __restrict__ W, unsigned char* __restrict__ blob,
                       int Cin, int CinP, int Cout) {
    int total = 27 * CinP * Cout;
    int idx = blockIdx.x * 256 + threadIdx.x;
    if (idx >= total) return;
    int ci = idx % CinP;
    int t = idx / CinP;
    int co = t % Cout;
    int k = t / Cout;
    float v = (ci < Cin) ? W[((size_t)k * Cin + ci) * Cout + co] : 0.f;
    __nv_bfloat16 h = __float2bfloat16_rn(v);
    __nv_bfloat16 l = __float2bfloat16_rn(v - __bfloat162float(h));
    int ch = ci >> 6, cic = ci & 63;
    int sw = (((cic >> 3) ^ (co & 7)) << 4) + (cic & 7) * 2;
    int NCH = CinP >> 6;
    size_t stageBase = (size_t)(k * NCH + ch) * (2 * Cout * 128);
    *(__nv_bfloat16*)(blob + stageBase + (size_t)co * 128 + sw) = h;
    *(__nv_bfloat16*)(blob + stageBase + (size_t)Cout * 128 + (size_t)co * 128 + sw) = l;
}

// ---------------------------------------------------------------------------
// Fused L0 conv1: Cin=3, Cout=64, fp32 out, skips missing neighbors.
// ---------------------------------------------------------------------------
__global__ __launch_bounds__(256) void k_conv0(const float* __restrict__ feats,
                                               const float* __restrict__ W,
                                               float* __restrict__ out,
                                               const int* __restrict__ np) {
    __shared__ float Ws[27 * 3 * 64];
    int n = *np;
    int tid = threadIdx.x;
    for (int e = tid; e < 27 * 3 * 64; e += 256) Ws[e] = W[e];
    __syncthreads();
    int r = blockIdx.x * 4 + (tid >> 6);
    int lane = tid & 63;
    if (r >= n) return;
    float acc = 0.f;
    #pragma unroll 1
    for (int k = 0; k < 27; k++) {
        int id = g_pairs[k * NMAX + r];
        if (id >= 0) {
            float f0 = feats[id * 3 + 0];
            float f1 = feats[id * 3 + 1];
            float f2 = feats[id * 3 + 2];
            const float* wk = Ws + k * 192;
            acc += f0 * wk[lane] + f1 * wk[64 + lane] + f2 * wk[128 + lane];
        }
    }
    out[(size_t)r * 64 + lane] = acc;
}

// ---------------------------------------------------------------------------
// L0 conv2: Cin=64, Cout=64, fp32, neighbor-skipping (density ~4.8%).
// ---------------------------------------------------------------------------
__global__ __launch_bounds__(256) void k_conv1s(const float* __restrict__ fin,
                                                const float* __restrict__ W,
                                                float* __restrict__ out,
                                                const int* __restrict__ np) {
    __shared__ float Wt[64][68];
    int n = *np;
    int tid = threadIdx.x;
    int rr = tid >> 6;
    int c  = tid & 63;
    int rowBase = blockIdx.x * 64;
    if (rowBase >= n) return;

    float acc[16];
    #pragma unroll
    for (int i = 0; i < 16; i++) acc[i] = 0.f;

    for (int k = 0; k < 27; k++) {
        __syncthreads();
        for (int e = tid; e < 4096; e += 256) {
            int ci = e >> 6, co = e & 63;
            Wt[co][ci] = W[k * 4096 + e];
        }
        __syncthreads();
        #pragma unroll 1
        for (int i = 0; i < 16; i++) {
            int r = rowBase + rr * 16 + i;
            if (r >= n) break;
            int id = g_pairs[k * NMAX + r];
            if (id < 0) continue;
            const float4* f4 = (const float4*)(fin + (size_t)id * 64);
            const float4* w4 = (const float4*)&Wt[c][0];
            float s = 0.f;
            #pragma unroll
            for (int q = 0; q < 16; q++) {
                float4 fv = f4[q];
                float4 wv = w4[q];
                s += fv.x * wv.x + fv.y * wv.y + fv.z * wv.z + fv.w * wv.w;
            }
            acc[i] += s;
        }
    }
    #pragma unroll
    for (int i = 0; i < 16; i++) {
        int r = rowBase + rr * 16 + i;
        if (r < n) out[(size_t)r * 64 + c] = acc[i];
    }
}

// ---------------------------------------------------------------------------
// mma.sync conv: 128-row tile x CoutS col slice, bf16x3 split fp32.
// 512 threads = 16 warps = 4 row-groups x 4 col-quarters.
// 3-stage cp.async pipeline; pair ids prefetched one stage ahead.
// Stage decode is GENERAL: k = s / NCH, ch = s % NCH (NCH can be 1, 2 or 3).
// ---------------------------------------------------------------------------
template <int NT>   // NT = CoutS/8, divisible by 4
__global__ __launch_bounds__(512) void k_wconv(
    const __nv_bfloat16* __restrict__ bhi, const __nv_bfloat16* __restrict__ blo,
    const unsigned char* __restrict__ wblob,
    float* __restrict__ outF,
    __nv_bfloat16* __restrict__ outH, __nv_bfloat16* __restrict__ outL, int CP,
    const int* __restrict__ np, int CinP, int CoutF)
{
    const int NT4 = NT / 4;
    const int CoutS = NT * 8;
    const int WstageS = 2 * CoutS * 128;
    int n = *np;
    int rowBase = blockIdx.x * 128;
    if (rowBase >= n) return;
    int colBase = blockIdx.y * CoutS;

    extern __shared__ __align__(1024) unsigned char sm[];
    const uint32_t Asm = smem_u32(sm);
    const uint32_t Wsm = Asm + 3 * 32768;

    int tid = threadIdx.x;
    int wid = tid >> 5;
    int lane = tid & 31;

    const int NCH = CinP >> 6;
    const int S = 27 * NCH;
    const int WstageF = 2 * CoutF * 128;

    int am = tid >> 2;
    int sub = tid & 3;
    int atile = sub >> 1;
    int ahalf = sub & 1;
    const __nv_bfloat16* Asrc = atile ? blo : bhi;
    int r_g = rowBase + am;

    float acc[2][NT4][4];
    #pragma unroll
    for (int mt = 0; mt < 2; mt++)
        #pragma unroll
        for (int j = 0; j < NT4; j++)
            #pragma unroll
            for (int q = 0; q < 4; q++) acc[mt][j][q] = 0.f;

    auto pairs_of = [&](int s) -> int {
        int k = s / NCH;                       // general (NCH ∈ {1,2,3})
        return (r_g < n) ? g_pairs[k * NMAX + r_g] : -1;
    };
    auto load_data = [&](int buf, int s, int id) {
        int k = s / NCH;
        int ch = s - k * NCH;
        {
            const unsigned char* src =
                (const unsigned char*)(Asrc + (size_t)(id < 0 ? 0 : id) * CinP + ch * 64)
                + ahalf * 64;
            uint32_t dst = Asm + buf * 32768 + atile * 16384 + am * 128;
            int m7 = (am & 7) << 4;
            int sz = (id >= 0) ? 16 : 0;
            #pragma unroll
            for (int c = 0; c < 4; c++) {
                int off = ahalf * 64 + c * 16;
                cp_async16(dst + (off ^ m7), src + c * 16, sz);
            }
        }
        {
            const unsigned char* src = wblob + (size_t)s * WstageF;
            const int hc = (CoutS * 128) >> 4;
            uint32_t dst = Wsm + buf * WstageS;
            for (int e = tid; e < 2 * hc; e += 512) {
                int half = (e >= hc) ? 1 : 0;
                int e2 = e - half * hc;
                const unsigned char* sp =
                    src + (size_t)((half ? (CoutF + colBase) : colBase)) * 128 + e2 * 16;
                cp_async16(dst + e * 16, sp, 16);
            }
        }
        cp_commit();
    };

    int rw = wid & 3;
    int cw = wid >> 2;
    int arow0 = rw * 32 + (lane & 15);
    int ac16 = (lane >> 4) & 1;
    int brow_l = lane & 7;
    int bc16 = (lane >> 3) & 1;

    // prologue: stages 0 and 1 in flight, id for stage 2 prefetched
    {
        int id0 = pairs_of(0);
        load_data(0, 0, id0);
    }
    {
        int id1 = pairs_of(1);
        load_data(1, 1, id1);
    }
    int idN = (S > 2) ? pairs_of(2) : -1;

    for (int s = 0; s < S; s++) {
        int b = s % 3;
        if (s + 2 < S) {
            load_data((s + 2) % 3, s + 2, idN);
            idN = (s + 3 < S) ? pairs_of(s + 3) : -1;
            asm volatile("cp.async.wait_group 2;\n");
        } else if (s + 1 < S) {
            asm volatile("cp.async.wait_group 1;\n");
        } else {
            asm volatile("cp.async.wait_group 0;\n");
        }
        __syncthreads();

        uint32_t AhB = Asm + b * 32768;
        uint32_t AlB = AhB + 16384;
        uint32_t WhB = Wsm + b * WstageS;
        uint32_t WlB = WhB + CoutS * 128;

        #pragma unroll
        for (int chunk = 0; chunk < 4; chunk++) {
            uint32_t ah[2][4], al[2][4];
            #pragma unroll
            for (int mt = 0; mt < 2; mt++) {
                uint32_t off = (uint32_t)(arow0 + mt * 16) * 128 + chunk * 32 + ac16 * 16;
                off ^= (off >> 3) & 0x70;
                ldsm4(ah[mt], AhB + off);
                ldsm4(al[mt], AlB + off);
            }
            #pragma unroll
            for (int j = 0; j < NT4; j++) {
                uint32_t off = (uint32_t)(cw * (NT4 * 8) + j * 8 + brow_l) * 128
                             + chunk * 32 + bc16 * 16;
                off ^= (off >> 3) & 0x70;
                uint32_t bh[2], bl[2];
                ldsm2(bh, WhB + off);
                ldsm2(bl, WlB + off);
                #pragma unroll
                for (int mt = 0; mt < 2; mt++) {
                    mma16816(acc[mt][j], ah[mt], bh);
                    mma16816(acc[mt][j], ah[mt], bl);
                    mma16816(acc[mt][j], al[mt], bh);
                }
            }
        }
        __syncthreads();
    }

    int grp = lane >> 2, tg = lane & 3;
    #pragma unroll
    for (int mt = 0; mt < 2; mt++) {
        int r0 = rowBase + rw * 32 + mt * 16 + grp;
        #pragma unroll
        for (int half = 0; half < 2; half++) {
            int r = r0 + half * 8;
            if (r >= n) continue;
            #pragma unroll
            for (int j = 0; j < NT4; j++) {
                float d0 = acc[mt][j][half * 2 + 0];
                float d1 = acc[mt][j][half * 2 + 1];
                int c = colBase + cw * (NT4 * 8) + j * 8 + tg * 2;
                if (outF) {
                    float2 v; v.x = d0; v.y = d1;
                    *(float2*)(outF + (size_t)r * CoutF + c) = v;
                }
                if (outH) {
                    __nv_bfloat16 h0 = __float2bfloat16_rn(d0);
                    __nv_bfloat16 h1 = __float2bfloat16_rn(d1);
                    __nv_bfloat16 l0 = __float2bfloat16_rn(d0 - __bfloat162float(h0));
                    __nv_bfloat16 l1 = __float2bfloat16_rn(d1 - __bfloat162float(h1));
                    uint32_t hp = ((uint32_t)(*(unsigned short*)&h1) << 16)
                                | (uint32_t)(*(unsigned short*)&h0);
                    uint32_t lp = ((uint32_t)(*(unsigned short*)&l1) << 16)
                                | (uint32_t)(*(unsigned short*)&l0);
                    *(uint32_t*)(outH + (size_t)r * CP + c) = hp;
                    *(uint32_t*)(outL + (size_t)r * CP + c) = lp;
                }
            }
            if (outH && blockIdx.y == 0 && cw == 0) {
                for (int c = CoutF + tg * 2; c < CP; c += 8) {
                    *(uint32_t*)(outH + (size_t)r * CP + c) = 0u;
                    *(uint32_t*)(outL + (size_t)r * CP + c) = 0u;
                }
            }
        }
    }
}

// ---------------------------------------------------------------------------
// Small-level scalar conv (n <= 512): 16 rows x 32 cols per block.
// ---------------------------------------------------------------------------
__global__ __launch_bounds__(256) void k_conv_small(const float* __restrict__ feats,
                                                    const float* __restrict__ W,
                                                    float* __restrict__ out,
                                                    const int* __restrict__ np,
                                                    int Cin, int Cout) {
    int n = *np;
    int rowBase = blockIdx.x * 16;
    if (rowBase >= n) return;
    int colBase = blockIdx.y * 32;

    __shared__ float As[16][33];
    __shared__ float Ws[32][33];

    int tid = threadIdx.x;
    int tm = tid >> 5;
    int tn = tid & 31;

    float acc0 = 0.f, acc1 = 0.f;

    for (int k = 0; k < 27; k++) {
        for (int c0 = 0; c0 < Cin; c0 += 32) {
            __syncthreads();
            {
                int e = tid;
                #pragma unroll
                for (int j = 0; j < 2; j++, e += 256) {
                    int m = e >> 5, c = e & 31;
                    int r = rowBase + m;
                    int id = (r < n) ? g_pairs[k * NMAX + r] : -1;
                    As[m][c] = (id >= 0) ? feats[(size_t)id * Cin + c0 + c] : 0.f;
                }
            }
            {
                const float* Wk = W + ((size_t)k * Cin + c0) * Cout + colBase;
                int e = tid;
                #pragma unroll
                for (int j = 0; j < 4; j++, e += 256) {
                    int kk = e >> 5, c = e & 31;
                    Ws[kk][c] = Wk[(size_t)kk * Cout + c];
                }
            }
            __syncthreads();
            #pragma unroll 8
            for (int kk = 0; kk < 32; kk++) {
                float w = Ws[kk][tn];
                acc0 += As[tm * 2][kk] * w;
                acc1 += As[tm * 2 + 1][kk] * w;
            }
        }
    }

    int r0 = rowBase + tm * 2;
    if (r0 < n)     out[(size_t)r0 * Cout + colBase + tn] = acc0;
    if (r0 + 1 < n) out[(size_t)(r0 + 1) * Cout + colBase + tn] = acc1;
}

// ---------------------------------------------------------------------------
// Pool structure kernels + pool with optional bf16 split output
// ---------------------------------------------------------------------------
__global__ void k_flags(const int* __restrict__ fineGrid, int S) {
    int Sc = S >> 1;
    int P = Sc * Sc * Sc;
    int p = blockIdx.x * blockDim.x + threadIdx.x;
    if (p >= P) return;
    int pz = p / (Sc * Sc);
    int rem = p - pz * Sc * Sc;
    int py = rem / Sc;
    int px = rem - py * Sc;
    int occ = 0;
    #pragma unroll
    for (int a = 0; a < 2; a++)
        #pragma unroll
        for (int b = 0; b < 2; b++)
            #pragma unroll
            for (int c = 0; c < 2; c++) {
                int l = ((2 * pz + a) * S + 2 * py + b) * S + 2 * px + c;
                if (fineGrid[l] >= 0) occ = 1;
            }
    g_flags[p] = occ;
}

__global__ void k_scanA(int P) {
    __shared__ int sh[256];
    int t = threadIdx.x;
    int base = blockIdx.x * 1024;
    int s = 0;
    #pragma unroll
    for (int j = 0; j < 4; j++) {
        int p = base + t * 4 + j;
        if (p < P) s += g_flags[p];
    }
    sh[t] = s;
    __syncthreads();
    for (int d = 128; d > 0; d >>= 1) {
        if (t < d) sh[t] += sh[t + d];
        __syncthreads();
    }
    if (t == 0) g_bsums[blockIdx.x] = sh[0];
}

__global__ void k_scanB(int nb, int Lnext) {
    __shared__ int sh[256];
    int t = threadIdx.x;
    int v = (t < nb) ? g_bsums[t] : 0;
    sh[t] = v;
    __syncthreads();
    for (int d = 1; d < 256; d <<= 1) {
        int x = (t >= d) ? sh[t - d] : 0;
        __syncthreads();
        sh[t] += x;
        __syncthreads();
    }
    if (t < nb) g_bsums[t] = sh[t] - v;
    if (t == 255) g_n[Lnext] = sh[255];
}

__global__ void k_scanC(int* __restrict__ coarseGrid, int* __restrict__ linNext, int P) {
    __shared__ int sh[256];
    int t = threadIdx.x;
    int base = blockIdx.x * 1024;
    int f[4];
    int s = 0;
    #pragma unroll
    for (int j = 0; j < 4; j++) {
        int p = base + t * 4 + j;
        f[j] = (p < P) ? g_flags[p] : 0;
        s += f[j];
    }
    int v = s;
    sh[t] = v;
    __syncthreads();
    for (int d = 1; d < 256; d <<= 1) {
        int x = (t >= d) ? sh[t - d] : 0;
        __syncthreads();
        sh[t] += x;
        __syncthreads();
    }
    int off = g_bsums[blockIdx.x] + sh[t] - v;
    #pragma unroll
    for (int j = 0; j < 4; j++) {
        int p = base + t * 4 + j;
        if (p >= P) break;
        if (f[j]) {
            coarseGrid[p] = off;
            linNext[off] = p;
            off++;
        } else {
            coarseGrid[p] = -1;
        }
    }
}

__global__ void k_pool2(const float* __restrict__ feats, float* __restrict__ out,
                        __nv_bfloat16* __restrict__ oh, __nv_bfloat16* __restrict__ ol,
                        const int* __restrict__ fineGrid, const int* __restrict__ linNext,
                        const int* __restrict__ np, int S, int C, int CP) {
    int row = blockIdx.x;
    if (row >= *np) return;
    int Sc = S >> 1;
    int p = linNext[row];
    int pz = p / (Sc * Sc);
    int rem = p - pz * Sc * Sc;
    int py = rem / Sc;
    int px = rem - py * Sc;
    int c = threadIdx.x;
    if (c < C) {
        float m = -3.4e38f;
        #pragma unroll
        for (int a = 0; a < 2; a++)
            #pragma unroll
            for (int b = 0; b < 2; b++)
                #pragma unroll
                for (int d = 0; d < 2; d++) {
                    int l = ((2 * pz + a) * S + 2 * py + b) * S + 2 * px + d;
                    int r = fineGrid[l];
                    if (r >= 0) m = fmaxf(m, feats[(size_t)r * C + c]);
                }
        out[(size_t)row * C + c] = m;
        if (CP) {
            __nv_bfloat16 h = __float2bfloat16_rn(m);
            oh[(size_t)row * CP + c] = h;
            ol[(size_t)row * CP + c] = __float2bfloat16_rn(m - __bfloat162float(h));
        }
    } else if (CP && c < CP) {
        oh[(size_t)row * CP + c] = __float2bfloat16_rn(0.f);
        ol[(size_t)row * CP + c] = __float2bfloat16_rn(0.f);
    }
}

// ---------------------------------------------------------------------------

static inline int ceildiv(int a, int b) { return (a + b - 1) / b; }
static inline int pad64(int c) { return (c + 63) & ~63; }

static void launch_wconv(const __nv_bfloat16* bhi, const __nv_bfloat16* blo,
                         const unsigned char* wb, float* outF,
                         __nv_bfloat16* oh, __nv_bfloat16* ol, int CP,
                         const int* np, int CinP, int Cout, int nBound, int gy) {
    int CoutS = Cout / gy;
    int NT = CoutS / 8;
    dim3 g(ceildiv(nBound, 128), gy), b(512);
    int smem = 3 * 32768 + 3 * 2 * CoutS * 128;
    switch (NT) {
        case 4:
            cudaFuncSetAttribute(k_wconv<4>, cudaFuncAttributeMaxDynamicSharedMemorySize, smem);
            k_wconv<4><<<g, b, smem>>>(bhi, blo, wb, outF, oh, ol, CP, np, CinP, Cout);
            break;
        case 8:
            cudaFuncSetAttribute(k_wconv<8>, cudaFuncAttributeMaxDynamicSharedMemorySize, smem);
            k_wconv<8><<<g, b, smem>>>(bhi, blo, wb, outF, oh, ol, CP, np, CinP, Cout);
            break;
        case 12:
            cudaFuncSetAttribute(k_wconv<12>, cudaFuncAttributeMaxDynamicSharedMemorySize, smem);
            k_wconv<12><<<g, b, smem>>>(bhi, blo, wb, outF, oh, ol, CP, np, CinP, Cout);
            break;
        case 16:
            cudaFuncSetAttribute(k_wconv<16>, cudaFuncAttributeMaxDynamicSharedMemorySize, smem);
            k_wconv<16><<<g, b, smem>>>(bhi, blo, wb, outF, oh, ol, CP, np, CinP, Cout);
            break;
    }
}

extern "C" void kernel_launch(void* const* d_in, const int* in_sizes, int n_in,
                              void* d_out, int out_size) {
    const float* feat_in = (const float*)d_in[0];
    const int*   coors   = (const int*)d_in[1];
    const float* w[14];
    for (int i = 0; i < 14; i++) w[i] = (const float*)d_in[3 + i];

    int n0 = in_sizes[0] / 3;

    float *fA, *fB;
    __nv_bfloat16 *bh1, *bl1, *bh2, *bl2;
    unsigned char* wblob;
    int *gA, *gB, *lA, *lB, *pn;
    cudaGetSymbolAddress((void**)&fA, g_featA);
    cudaGetSymbolAddress((void**)&fB, g_featB);
    cudaGetSymbolAddress((void**)&bh1, g_bh1);
    cudaGetSymbolAddress((void**)&bl1, g_bl1);
    cudaGetSymbolAddress((void**)&bh2, g_bh2);
    cudaGetSymbolAddress((void**)&bl2, g_bl2);
    cudaGetSymbolAddress((void**)&wblob, g_wblob);
    cudaGetSymbolAddress((void**)&gA, g_gridA);
    cudaGetSymbolAddress((void**)&gB, g_gridB);
    cudaGetSymbolAddress((void**)&lA, g_linA);
    cudaGetSymbolAddress((void**)&lB, g_linB);
    cudaGetSymbolAddress((void**)&pn, g_n);

    const int S[7]  = {128, 64, 32, 16, 8, 4, 2};
    int NB[7];
    NB[0] = n0;
    NB[1] = n0 < (64 * 64 * 64) ? n0 : (64 * 64 * 64);
    NB[2] = 32 * 32 * 32;
    NB[3] = 16 * 16 * 16;
    NB[4] = 8 * 8 * 8;
    NB[5] = 4 * 4 * 4;
    NB[6] = 2 * 2 * 2;
    const int Cin1[7]  = {3, 64, 96, 128, 160, 192, 224};
    const int Cout1[7] = {64, 96, 128, 160, 192, 224, 256};

    // MMA-path layers (indices 2..7 == L1c1..L3c2)
    const int LCin[8]  = {3, 64, 64, 96, 96, 128, 128, 160};
    const int LCinP[8] = {64, 64, 64, 128, 128, 128, 128, 192};
    const int LCout[8] = {64, 64, 96, 96, 128, 128, 160, 160};
    size_t woff[9];
    woff[0] = 0;
    for (int i = 0; i < 8; i++)
        woff[i + 1] = woff[i] + (size_t)27 * (LCinP[i] / 64) * 2 * LCout[i] * 128;

    // ---- level-0 structure ----
    k_setn<<<1, 1>>>(n0);
    k_fill<<<ceildiv(GRID_CELLS, 256), 256>>>(gA, -1, GRID_CELLS);
    k_scatter0<<<ceildiv(n0, 256), 256>>>(coors, n0);

    int* linCur = lA;
    int* gridCur = gA;
    int* linNxt = lB;
    int* gridNxt = gB;

    // ---- L0: pairs, scalar conv1 + conv2 (fp32, neighbor skipping) ----
    k_pairs<<<ceildiv(NB[0], 256), 256>>>(linCur, gridCur, pn, S[0]);
    k_conv0<<<ceildiv(NB[0], 4), 256>>>(feat_in, w[0], fA, pn);

    // weight blob for MMA layers 2..7
    for (int i = 2; i < 8; i++) {
        int total = 27 * LCinP[i] * LCout[i];
        k_wcvt<<<ceildiv(total, 256), 256>>>(w[i], wblob + woff[i],
                                             LCin[i], LCinP[i], LCout[i]);
    }

    k_conv1s<<<ceildiv(NB[0], 64), 256>>>(fA, w[1], fB, pn);

    // pool0: fB -> fA (fp32) + bh1/bl1 split (CP = LCinP[2] = 64)
    {
        int Sc = S[0] >> 1, P = Sc * Sc * Sc, nb = ceildiv(P, 1024);
        k_flags<<<ceildiv(P, 256), 256>>>(gridCur, S[0]);
        k_scanA<<<nb, 256>>>(P);
        k_scanB<<<1, 256>>>(nb, 1);
        k_scanC<<<nb, 256>>>(gridNxt, linNxt, P);
        k_pool2<<<NB[1], 64>>>(fB, fA, bh1, bl1, gridCur, linNxt, pn + 1, S[0], 64, 64);
        int* t;
        t = linCur; linCur = linNxt; linNxt = t;
        t = gridCur; gridCur = gridNxt; gridNxt = t;
    }

    // ---- MMA levels 1..3 ----
    for (int L = 1; L < 4; L++) {
        const int* np = pn + L;
        k_pairs<<<ceildiv(NB[L], 256), 256>>>(linCur, gridCur, np, S[L]);

        int li1 = 2 * L, li2 = 2 * L + 1;
        int gy = (L == 3) ? 5 : 1;
        launch_wconv(bh1, bl1, wblob + woff[li1], nullptr, bh2, bl2, LCinP[li2],
                     np, LCinP[li1], LCout[li1], NB[L], gy);
        launch_wconv(bh2, bl2, wblob + woff[li2], fB, nullptr, nullptr, 0,
                     np, LCinP[li2], LCout[li2], NB[L], gy);

        {
            int Sc = S[L] >> 1, P = Sc * Sc * Sc, nb = ceildiv(P, 1024);
            k_flags<<<ceildiv(P, 256), 256>>>(gridCur, S[L]);
            k_scanA<<<nb, 256>>>(P);
            k_scanB<<<1, 256>>>(nb, L + 1);
            k_scanC<<<nb, 256>>>(gridNxt, linNxt, P);
            int C = LCout[li2];
            int CP = (L < 3) ? pad64(C) : 0;
            int thr = CP ? CP : C;
            k_pool2<<<NB[L + 1], thr>>>(fB, fA, bh1, bl1, gridCur, linNxt,
                                        pn + L + 1, S[L], C, CP);
        }
        int* t;
        t = linCur; linCur = linNxt; linNxt = t;
        t = gridCur; gridCur = gridNxt; gridNxt = t;
    }

    // ---- FFMA levels 4..6 (pool L3 output in fA) ----
    const float* cur = fA;
    for (int L = 4; L < 7; L++) {
        const int* np = pn + L;
        k_pairs<<<ceildiv(NB[L], 256), 256>>>(linCur, gridCur, np, S[L]);
        int ci1 = Cin1[L], co1 = Cout1[L];
        float* o1 = (cur == fA) ? fB : fA;
        {
            dim3 g(ceildiv(NB[L], 16), co1 / 32), b(256);
            k_conv_small<<<g, b>>>(cur, w[2 * L], o1, np, ci1, co1);
        }
        float* o2 = (L == 6) ? (float*)d_out : ((o1 == fA) ? fB : fA);
        {
            dim3 g(ceildiv(NB[L], 16), co1 / 32), b(256);
            k_conv_small<<<g, b>>>(o1, w[2 * L + 1], o2, np, co1, co1);
        }
        cur = o2;
        if (L < 6) {
            int Sc = S[L] >> 1, P = Sc * Sc * Sc, nb = ceildiv(P, 1024);
            k_flags<<<ceildiv(P, 256), 256>>>(gridCur, S[L]);
            k_scanA<<<nb, 256>>>(P);
            k_scanB<<<1, 256>>>(nb, L + 1);
            k_scanC<<<nb, 256>>>(gridNxt, linNxt, P);
            float* po = (cur == fA) ? fB : fA;
            k_pool2<<<NB[L + 1], co1>>>(cur, po, nullptr, nullptr, gridCur, linNxt,
                                        pn + L + 1, S[L], co1, 0);
            cur = po;
            int* t;
            t = linCur; linCur = linNxt; linNxt = t;
            t = gridCur; gridCur = gridNxt; gridNxt = t;
        }
    }
}

// round 10
// speedup vs baseline: 1.0461x; 1.0461x over previous
#include <cuda_runtime.h>
#include <cuda_bf16.h>
#include <cstdint>

// ---------------------------------------------------------------------------
// Sparse submanifold 3D conv backbone, batch=1, 128^3 -> 2^3.
// L0 conv1+conv2 (density 4.8%): neighbor-skipping scalar fp32 kernels.
// L1..L3: mma.sync bf16x3 split-fp32, 2-stage cp.async pipeline.
// Levels 4-6 (n <= 512): scalar FFMA path.
// ---------------------------------------------------------------------------

#define NMAX 100000
#define GRID_CELLS (1 << 21)
#define FLAGS_MAX (1 << 18)

__device__ int   g_n[8];
__device__ int   g_linA[NMAX];
__device__ int   g_linB[NMAX];
__device__ int   g_gridA[GRID_CELLS];
__device__ int   g_gridB[GRID_CELLS];
__device__ int   g_pairs[27 * NMAX];
__device__ int   g_flags[FLAGS_MAX];
__device__ int   g_bsums[256];
__device__ __align__(1024) float g_featA[10000000];
__device__ __align__(1024) float g_featB[10000000];
// bf16 hi/lo feature tables: pair-1 = conv1 input, pair-2 = conv2 input
__device__ __align__(1024) __nv_bfloat16 g_bh1[12000000];
__device__ __align__(1024) __nv_bfloat16 g_bl1[12000000];
__device__ __align__(1024) __nv_bfloat16 g_bh2[12000000];
__device__ __align__(1024) __nv_bfloat16 g_bl2[12000000];
// pre-swizzled, transposed, split weight blob (layers 2..7)
__device__ __align__(1024) unsigned char g_wblob[16 * 1024 * 1024];

// ---------------------------------------------------------------------------

__device__ __forceinline__ void cp_async16(uint32_t dst, const void* src, int srcBytes) {
    asm volatile("cp.async.cg.shared.global [%0], [%1], 16, %2;\n"
                 :: "r"(dst), "l"(src), "r"(srcBytes));
}
__device__ __forceinline__ void cp_commit() {
    asm volatile("cp.async.commit_group;\n");
}
__device__ __forceinline__ uint32_t smem_u32(const void* p) {
    uint32_t a;
    asm("{ .reg .u64 t; cvta.to.shared.u64 t, %1; cvt.u32.u64 %0, t; }" : "=r"(a) : "l"(p));
    return a;
}
__device__ __forceinline__ void ldsm4(uint32_t* r, uint32_t addr) {
    asm volatile("ldmatrix.sync.aligned.m8n8.x4.shared.b16 {%0,%1,%2,%3}, [%4];"
                 : "=r"(r[0]), "=r"(r[1]), "=r"(r[2]), "=r"(r[3]) : "r"(addr));
}
__device__ __forceinline__ void ldsm2(uint32_t* r, uint32_t addr) {
    asm volatile("ldmatrix.sync.aligned.m8n8.x2.shared.b16 {%0,%1}, [%2];"
                 : "=r"(r[0]), "=r"(r[1]) : "r"(addr));
}
__device__ __forceinline__ void mma16816(float* d, const uint32_t* a, const uint32_t* b) {
    asm volatile("mma.sync.aligned.m16n8k16.row.col.f32.bf16.bf16.f32 "
                 "{%0,%1,%2,%3}, {%4,%5,%6,%7}, {%8,%9}, {%0,%1,%2,%3};"
                 : "+f"(d[0]), "+f"(d[1]), "+f"(d[2]), "+f"(d[3])
                 : "r"(a[0]), "r"(a[1]), "r"(a[2]), "r"(a[3]), "r"(b[0]), "r"(b[1]));
}

// ---------------------------------------------------------------------------

__global__ void k_setn(int n0) { g_n[0] = n0; }

__global__ void k_fill(int* g, int v, int P) {
    int i = blockIdx.x * blockDim.x + threadIdx.x;
    if (i < P) g[i] = v;
}

__global__ void k_scatter0(const int* __restrict__ coors, int n0) {
    int i = blockIdx.x * blockDim.x + threadIdx.x;
    if (i >= n0) return;
    int z = coors[i * 4 + 1];
    int y = coors[i * 4 + 2];
    int x = coors[i * 4 + 3];
    int l = (z * 128 + y) * 128 + x;
    g_linA[i] = l;
    g_gridA[l] = i;
}

__global__ void k_pairs(const int* __restrict__ lin, const int* __restrict__ grid,
                        const int* __restrict__ np, int S) {
    int n = *np;
    int i = blockIdx.x * blockDim.x + threadIdx.x;
    if (i >= n) return;
    int l = lin[i];
    int z = l / (S * S);
    int rem = l - z * S * S;
    int y = rem / S;
    int x = rem - y * S;
    int k = 0;
    #pragma unroll
    for (int dz = -1; dz <= 1; dz++)
        #pragma unroll
        for (int dy = -1; dy <= 1; dy++)
            #pragma unroll
            for (int dx = -1; dx <= 1; dx++) {
                int zz = z + dz, yy = y + dy, xx = x + dx;
                int v = -1;
                if (zz >= 0 && zz < S && yy >= 0 && yy < S && xx >= 0 && xx < S)
                    v = grid[(zz * S + yy) * S + xx];
                g_pairs[k * NMAX + i] = v;
                k++;
            }
}

// Weight blob: W[27,Cin,Cout] fp32 -> per-stage SW128 images of W^T
// [Cout rows x 64 cols] bf16, hi then lo. Stage = (k, ci-chunk).
__global__ void k_wcvt(const float* __restrict__ W, unsigned char* __restrict__ blob,
                       int Cin, int CinP, int Cout) {
    int total = 27 * CinP * Cout;
    int idx = blockIdx.x * 256 + threadIdx.x;
    if (idx >= total) return;
    int ci = idx % CinP;
    int t = idx / CinP;
    int co = t % Cout;
    int k = t / Cout;
    float v = (ci < Cin) ? W[((size_t)k * Cin + ci) * Cout + co] : 0.f;
    __nv_bfloat16 h = __float2bfloat16_rn(v);
    __nv_bfloat16 l = __float2bfloat16_rn(v - __bfloat162float(h));
    int ch = ci >> 6, cic = ci & 63;
    int sw = (((cic >> 3) ^ (co & 7)) << 4) + (cic & 7) * 2;
    int NCH = CinP >> 6;
    size_t stageBase = (size_t)(k * NCH + ch) * (2 * Cout * 128);
    *(__nv_bfloat16*)(blob + stageBase + (size_t)co * 128 + sw) = h;
    *(__nv_bfloat16*)(blob + stageBase + (size_t)Cout * 128 + (size_t)co * 128 + sw) = l;
}

// ---------------------------------------------------------------------------
// Fused L0 conv1: Cin=3, Cout=64, fp32 out, skips missing neighbors.
// ---------------------------------------------------------------------------
__global__ __launch_bounds__(256) void k_conv0(const float* __restrict__ feats,
                                               const float* __restrict__ W,
                                               float* __restrict__ out,
                                               const int* __restrict__ np) {
    __shared__ float Ws[27 * 3 * 64];
    int n = *np;
    int tid = threadIdx.x;
    for (int e = tid; e < 27 * 3 * 64; e += 256) Ws[e] = W[e];
    __syncthreads();
    int r = blockIdx.x * 4 + (tid >> 6);
    int lane = tid & 63;
    if (r >= n) return;
    float acc = 0.f;
    #pragma unroll 1
    for (int k = 0; k < 27; k++) {
        int id = g_pairs[k * NMAX + r];
        if (id >= 0) {
            float f0 = feats[id * 3 + 0];
            float f1 = feats[id * 3 + 1];
            float f2 = feats[id * 3 + 2];
            const float* wk = Ws + k * 192;
            acc += f0 * wk[lane] + f1 * wk[64 + lane] + f2 * wk[128 + lane];
        }
    }
    out[(size_t)r * 64 + lane] = acc;
}

// ---------------------------------------------------------------------------
// L0 conv2: Cin=64, Cout=64, fp32, neighbor-skipping (density ~4.8%).
// ---------------------------------------------------------------------------
__global__ __launch_bounds__(256) void k_conv1s(const float* __restrict__ fin,
                                                const float* __restrict__ W,
                                                float* __restrict__ out,
                                                const int* __restrict__ np) {
    __shared__ float Wt[64][68];
    int n = *np;
    int tid = threadIdx.x;
    int rr = tid >> 6;
    int c  = tid & 63;
    int rowBase = blockIdx.x * 64;
    if (rowBase >= n) return;

    float acc[16];
    #pragma unroll
    for (int i = 0; i < 16; i++) acc[i] = 0.f;

    for (int k = 0; k < 27; k++) {
        __syncthreads();
        for (int e = tid; e < 4096; e += 256) {
            int ci = e >> 6, co = e & 63;
            Wt[co][ci] = W[k * 4096 + e];
        }
        __syncthreads();
        #pragma unroll 1
        for (int i = 0; i < 16; i++) {
            int r = rowBase + rr * 16 + i;
            if (r >= n) break;
            int id = g_pairs[k * NMAX + r];
            if (id < 0) continue;
            const float4* f4 = (const float4*)(fin + (size_t)id * 64);
            const float4* w4 = (const float4*)&Wt[c][0];
            float s = 0.f;
            #pragma unroll
            for (int q = 0; q < 16; q++) {
                float4 fv = f4[q];
                float4 wv = w4[q];
                s += fv.x * wv.x + fv.y * wv.y + fv.z * wv.z + fv.w * wv.w;
            }
            acc[i] += s;
        }
    }
    #pragma unroll
    for (int i = 0; i < 16; i++) {
        int r = rowBase + rr * 16 + i;
        if (r < n) out[(size_t)r * 64 + c] = acc[i];
    }
}

// ---------------------------------------------------------------------------
// mma.sync conv: 128-row tile x CoutS col slice, bf16x3 split fp32.
// 512 threads = 16 warps = 4 row-groups x 4 col-quarters.
// 2-stage cp.async pipeline; general stage decode (NCH in {1,2,3}).
// ---------------------------------------------------------------------------
template <int NT>   // NT = CoutS/8, divisible by 4
__global__ __launch_bounds__(512) void k_wconv(
    const __nv_bfloat16* __restrict__ bhi, const __nv_bfloat16* __restrict__ blo,
    const unsigned char* __restrict__ wblob,
    float* __restrict__ outF,
    __nv_bfloat16* __restrict__ outH, __nv_bfloat16* __restrict__ outL, int CP,
    const int* __restrict__ np, int CinP, int CoutF)
{
    const int NT4 = NT / 4;
    const int CoutS = NT * 8;
    const int WstageS = 2 * CoutS * 128;
    int n = *np;
    int rowBase = blockIdx.x * 128;
    if (rowBase >= n) return;
    int colBase = blockIdx.y * CoutS;

    extern __shared__ __align__(1024) unsigned char sm[];
    const uint32_t Asm = smem_u32(sm);
    const uint32_t Wsm = Asm + 2 * 32768;

    int tid = threadIdx.x;
    int wid = tid >> 5;
    int lane = tid & 31;

    const int NCH = CinP >> 6;
    const int S = 27 * NCH;
    const int WstageF = 2 * CoutF * 128;

    int am = tid >> 2;
    int sub = tid & 3;
    int atile = sub >> 1;
    int ahalf = sub & 1;
    const __nv_bfloat16* Asrc = atile ? blo : bhi;
    int r_g = rowBase + am;
    int curK = -1, curId = -1;

    float acc[2][NT4][4];
    #pragma unroll
    for (int mt = 0; mt < 2; mt++)
        #pragma unroll
        for (int j = 0; j < NT4; j++)
            #pragma unroll
            for (int q = 0; q < 4; q++) acc[mt][j][q] = 0.f;

    auto load = [&](int buf, int s) {
        int k = s / NCH;
        int ch = s - k * NCH;
        if (k != curK) {
            curK = k;
            curId = (r_g < n) ? g_pairs[k * NMAX + r_g] : -1;
        }
        {
            const unsigned char* src =
                (const unsigned char*)(Asrc + (size_t)(curId < 0 ? 0 : curId) * CinP + ch * 64)
                + ahalf * 64;
            uint32_t dst = Asm + buf * 32768 + atile * 16384 + am * 128;
            int m7 = (am & 7) << 4;
            int sz = (curId >= 0) ? 16 : 0;
            #pragma unroll
            for (int c = 0; c < 4; c++) {
                int off = ahalf * 64 + c * 16;
                cp_async16(dst + (off ^ m7), src + c * 16, sz);
            }
        }
        {
            const unsigned char* src = wblob + (size_t)s * WstageF;
            const int hc = (CoutS * 128) >> 4;
            uint32_t dst = Wsm + buf * WstageS;
            for (int e = tid; e < 2 * hc; e += 512) {
                int half = (e >= hc) ? 1 : 0;
                int e2 = e - half * hc;
                const unsigned char* sp =
                    src + (size_t)((half ? (CoutF + colBase) : colBase)) * 128 + e2 * 16;
                cp_async16(dst + e * 16, sp, 16);
            }
        }
        cp_commit();
    };

    int rw = wid & 3;
    int cw = wid >> 2;
    int arow0 = rw * 32 + (lane & 15);
    int ac16 = (lane >> 4) & 1;
    int brow_l = lane & 7;
    int bc16 = (lane >> 3) & 1;

    load(0, 0);
    for (int s = 0; s < S; s++) {
        int b = s & 1;
        if (s + 1 < S) {
            load(b ^ 1, s + 1);
            asm volatile("cp.async.wait_group 1;\n");
        } else {
            asm volatile("cp.async.wait_group 0;\n");
        }
        __syncthreads();

        uint32_t AhB = Asm + b * 32768;
        uint32_t AlB = AhB + 16384;
        uint32_t WhB = Wsm + b * WstageS;
        uint32_t WlB = WhB + CoutS * 128;

        #pragma unroll
        for (int chunk = 0; chunk < 4; chunk++) {
            uint32_t ah[2][4], al[2][4];
            #pragma unroll
            for (int mt = 0; mt < 2; mt++) {
                uint32_t off = (uint32_t)(arow0 + mt * 16) * 128 + chunk * 32 + ac16 * 16;
                off ^= (off >> 3) & 0x70;
                ldsm4(ah[mt], AhB + off);
                ldsm4(al[mt], AlB + off);
            }
            #pragma unroll
            for (int j = 0; j < NT4; j++) {
                uint32_t off = (uint32_t)(cw * (NT4 * 8) + j * 8 + brow_l) * 128
                             + chunk * 32 + bc16 * 16;
                off ^= (off >> 3) & 0x70;
                uint32_t bh[2], bl[2];
                ldsm2(bh, WhB + off);
                ldsm2(bl, WlB + off);
                #pragma unroll
                for (int mt = 0; mt < 2; mt++) {
                    mma16816(acc[mt][j], ah[mt], bh);
                    mma16816(acc[mt][j], ah[mt], bl);
                    mma16816(acc[mt][j], al[mt], bh);
                }
            }
        }
        __syncthreads();
    }

    int grp = lane >> 2, tg = lane & 3;
    #pragma unroll
    for (int mt = 0; mt < 2; mt++) {
        int r0 = rowBase + rw * 32 + mt * 16 + grp;
        #pragma unroll
        for (int half = 0; half < 2; half++) {
            int r = r0 + half * 8;
            if (r >= n) continue;
            #pragma unroll
            for (int j = 0; j < NT4; j++) {
                float d0 = acc[mt][j][half * 2 + 0];
                float d1 = acc[mt][j][half * 2 + 1];
                int c = colBase + cw * (NT4 * 8) + j * 8 + tg * 2;
                if (outF) {
                    float2 v; v.x = d0; v.y = d1;
                    *(float2*)(outF + (size_t)r * CoutF + c) = v;
                }
                if (outH) {
                    __nv_bfloat16 h0 = __float2bfloat16_rn(d0);
                    __nv_bfloat16 h1 = __float2bfloat16_rn(d1);
                    __nv_bfloat16 l0 = __float2bfloat16_rn(d0 - __bfloat162float(h0));
                    __nv_bfloat16 l1 = __float2bfloat16_rn(d1 - __bfloat162float(h1));
                    uint32_t hp = ((uint32_t)(*(unsigned short*)&h1) << 16)
                                | (uint32_t)(*(unsigned short*)&h0);
                    uint32_t lp = ((uint32_t)(*(unsigned short*)&l1) << 16)
                                | (uint32_t)(*(unsigned short*)&l0);
                    *(uint32_t*)(outH + (size_t)r * CP + c) = hp;
                    *(uint32_t*)(outL + (size_t)r * CP + c) = lp;
                }
            }
            if (outH && blockIdx.y == 0 && cw == 0) {
                for (int c = CoutF + tg * 2; c < CP; c += 8) {
                    *(uint32_t*)(outH + (size_t)r * CP + c) = 0u;
                    *(uint32_t*)(outL + (size_t)r * CP + c) = 0u;
                }
            }
        }
    }
}

// ---------------------------------------------------------------------------
// Small-level scalar conv (n <= 512): 16 rows x 32 cols per block.
// ---------------------------------------------------------------------------
__global__ __launch_bounds__(256) void k_conv_small(const float* __restrict__ feats,
                                                    const float* __restrict__ W,
                                                    float* __restrict__ out,
                                                    const int* __restrict__ np,
                                                    int Cin, int Cout) {
    int n = *np;
    int rowBase = blockIdx.x * 16;
    if (rowBase >= n) return;
    int colBase = blockIdx.y * 32;

    __shared__ float As[16][33];
    __shared__ float Ws[32][33];

    int tid = threadIdx.x;
    int tm = tid >> 5;
    int tn = tid & 31;

    float acc0 = 0.f, acc1 = 0.f;

    for (int k = 0; k < 27; k++) {
        for (int c0 = 0; c0 < Cin; c0 += 32) {
            __syncthreads();
            {
                int e = tid;
                #pragma unroll
                for (int j = 0; j < 2; j++, e += 256) {
                    int m = e >> 5, c = e & 31;
                    int r = rowBase + m;
                    int id = (r < n) ? g_pairs[k * NMAX + r] : -1;
                    As[m][c] = (id >= 0) ? feats[(size_t)id * Cin + c0 + c] : 0.f;
                }
            }
            {
                const float* Wk = W + ((size_t)k * Cin + c0) * Cout + colBase;
                int e = tid;
                #pragma unroll
                for (int j = 0; j < 4; j++, e += 256) {
                    int kk = e >> 5, c = e & 31;
                    Ws[kk][c] = Wk[(size_t)kk * Cout + c];
                }
            }
            __syncthreads();
            #pragma unroll 8
            for (int kk = 0; kk < 32; kk++) {
                float w = Ws[kk][tn];
                acc0 += As[tm * 2][kk] * w;
                acc1 += As[tm * 2 + 1][kk] * w;
            }
        }
    }

    int r0 = rowBase + tm * 2;
    if (r0 < n)     out[(size_t)r0 * Cout + colBase + tn] = acc0;
    if (r0 + 1 < n) out[(size_t)(r0 + 1) * Cout + colBase + tn] = acc1;
}

// ---------------------------------------------------------------------------
// Pool structure kernels + pool with optional bf16 split output
// ---------------------------------------------------------------------------
__global__ void k_flags(const int* __restrict__ fineGrid, int S) {
    int Sc = S >> 1;
    int P = Sc * Sc * Sc;
    int p = blockIdx.x * blockDim.x + threadIdx.x;
    if (p >= P) return;
    int pz = p / (Sc * Sc);
    int rem = p - pz * Sc * Sc;
    int py = rem / Sc;
    int px = rem - py * Sc;
    int occ = 0;
    #pragma unroll
    for (int a = 0; a < 2; a++)
        #pragma unroll
        for (int b = 0; b < 2; b++)
            #pragma unroll
            for (int c = 0; c < 2; c++) {
                int l = ((2 * pz + a) * S + 2 * py + b) * S + 2 * px + c;
                if (fineGrid[l] >= 0) occ = 1;
            }
    g_flags[p] = occ;
}

__global__ void k_scanA(int P) {
    __shared__ int sh[256];
    int t = threadIdx.x;
    int base = blockIdx.x * 1024;
    int s = 0;
    #pragma unroll
    for (int j = 0; j < 4; j++) {
        int p = base + t * 4 + j;
        if (p < P) s += g_flags[p];
    }
    sh[t] = s;
    __syncthreads();
    for (int d = 128; d > 0; d >>= 1) {
        if (t < d) sh[t] += sh[t + d];
        __syncthreads();
    }
    if (t == 0) g_bsums[blockIdx.x] = sh[0];
}

__global__ void k_scanB(int nb, int Lnext) {
    __shared__ int sh[256];
    int t = threadIdx.x;
    int v = (t < nb) ? g_bsums[t] : 0;
    sh[t] = v;
    __syncthreads();
    for (int d = 1; d < 256; d <<= 1) {
        int x = (t >= d) ? sh[t - d] : 0;
        __syncthreads();
        sh[t] += x;
        __syncthreads();
    }
    if (t < nb) g_bsums[t] = sh[t] - v;
    if (t == 255) g_n[Lnext] = sh[255];
}

__global__ void k_scanC(int* __restrict__ coarseGrid, int* __restrict__ linNext, int P) {
    __shared__ int sh[256];
    int t = threadIdx.x;
    int base = blockIdx.x * 1024;
    int f[4];
    int s = 0;
    #pragma unroll
    for (int j = 0; j < 4; j++) {
        int p = base + t * 4 + j;
        f[j] = (p < P) ? g_flags[p] : 0;
        s += f[j];
    }
    int v = s;
    sh[t] = v;
    __syncthreads();
    for (int d = 1; d < 256; d <<= 1) {
        int x = (t >= d) ? sh[t - d] : 0;
        __syncthreads();
        sh[t] += x;
        __syncthreads();
    }
    int off = g_bsums[blockIdx.x] + sh[t] - v;
    #pragma unroll
    for (int j = 0; j < 4; j++) {
        int p = base + t * 4 + j;
        if (p >= P) break;
        if (f[j]) {
            coarseGrid[p] = off;
            linNext[off] = p;
            off++;
        } else {
            coarseGrid[p] = -1;
        }
    }
}

__global__ void k_pool2(const float* __restrict__ feats, float* __restrict__ out,
                        __nv_bfloat16* __restrict__ oh, __nv_bfloat16* __restrict__ ol,
                        const int* __restrict__ fineGrid, const int* __restrict__ linNext,
                        const int* __restrict__ np, int S, int C, int CP) {
    int row = blockIdx.x;
    if (row >= *np) return;
    int Sc = S >> 1;
    int p = linNext[row];
    int pz = p / (Sc * Sc);
    int rem = p - pz * Sc * Sc;
    int py = rem / Sc;
    int px = rem - py * Sc;
    int c = threadIdx.x;
    if (c < C) {
        float m = -3.4e38f;
        #pragma unroll
        for (int a = 0; a < 2; a++)
            #pragma unroll
            for (int b = 0; b < 2; b++)
                #pragma unroll
                for (int d = 0; d < 2; d++) {
                    int l = ((2 * pz + a) * S + 2 * py + b) * S + 2 * px + d;
                    int r = fineGrid[l];
                    if (r >= 0) m = fmaxf(m, feats[(size_t)r * C + c]);
                }
        out[(size_t)row * C + c] = m;
        if (CP) {
            __nv_bfloat16 h = __float2bfloat16_rn(m);
            oh[(size_t)row * CP + c] = h;
            ol[(size_t)row * CP + c] = __float2bfloat16_rn(m - __bfloat162float(h));
        }
    } else if (CP && c < CP) {
        oh[(size_t)row * CP + c] = __float2bfloat16_rn(0.f);
        ol[(size_t)row * CP + c] = __float2bfloat16_rn(0.f);
    }
}

// ---------------------------------------------------------------------------

static inline int ceildiv(int a, int b) { return (a + b - 1) / b; }
static inline int pad64(int c) { return (c + 63) & ~63; }

static void launch_wconv(const __nv_bfloat16* bhi, const __nv_bfloat16* blo,
                         const unsigned char* wb, float* outF,
                         __nv_bfloat16* oh, __nv_bfloat16* ol, int CP,
                         const int* np, int CinP, int Cout, int nBound, int gy) {
    int CoutS = Cout / gy;
    int NT = CoutS / 8;
    dim3 g(ceildiv(nBound, 128), gy), b(512);
    int smem = 2 * 32768 + 2 * 2 * CoutS * 128;
    switch (NT) {
        case 4:
            cudaFuncSetAttribute(k_wconv<4>, cudaFuncAttributeMaxDynamicSharedMemorySize, smem);
            k_wconv<4><<<g, b, smem>>>(bhi, blo, wb, outF, oh, ol, CP, np, CinP, Cout);
            break;
        case 8:
            cudaFuncSetAttribute(k_wconv<8>, cudaFuncAttributeMaxDynamicSharedMemorySize, smem);
            k_wconv<8><<<g, b, smem>>>(bhi, blo, wb, outF, oh, ol, CP, np, CinP, Cout);
            break;
        case 12:
            cudaFuncSetAttribute(k_wconv<12>, cudaFuncAttributeMaxDynamicSharedMemorySize, smem);
            k_wconv<12><<<g, b, smem>>>(bhi, blo, wb, outF, oh, ol, CP, np, CinP, Cout);
            break;
        case 16:
            cudaFuncSetAttribute(k_wconv<16>, cudaFuncAttributeMaxDynamicSharedMemorySize, smem);
            k_wconv<16><<<g, b, smem>>>(bhi, blo, wb, outF, oh, ol, CP, np, CinP, Cout);
            break;
    }
}

extern "C" void kernel_launch(void* const* d_in, const int* in_sizes, int n_in,
                              void* d_out, int out_size) {
    const float* feat_in = (const float*)d_in[0];
    const int*   coors   = (const int*)d_in[1];
    const float* w[14];
    for (int i = 0; i < 14; i++) w[i] = (const float*)d_in[3 + i];

    int n0 = in_sizes[0] / 3;

    float *fA, *fB;
    __nv_bfloat16 *bh1, *bl1, *bh2, *bl2;
    unsigned char* wblob;
    int *gA, *gB, *lA, *lB, *pn;
    cudaGetSymbolAddress((void**)&fA, g_featA);
    cudaGetSymbolAddress((void**)&fB, g_featB);
    cudaGetSymbolAddress((void**)&bh1, g_bh1);
    cudaGetSymbolAddress((void**)&bl1, g_bl1);
    cudaGetSymbolAddress((void**)&bh2, g_bh2);
    cudaGetSymbolAddress((void**)&bl2, g_bl2);
    cudaGetSymbolAddress((void**)&wblob, g_wblob);
    cudaGetSymbolAddress((void**)&gA, g_gridA);
    cudaGetSymbolAddress((void**)&gB, g_gridB);
    cudaGetSymbolAddress((void**)&lA, g_linA);
    cudaGetSymbolAddress((void**)&lB, g_linB);
    cudaGetSymbolAddress((void**)&pn, g_n);

    const int S[7]  = {128, 64, 32, 16, 8, 4, 2};
    int NB[7];
    NB[0] = n0;
    NB[1] = n0 < (64 * 64 * 64) ? n0 : (64 * 64 * 64);
    NB[2] = 32 * 32 * 32;
    NB[3] = 16 * 16 * 16;
    NB[4] = 8 * 8 * 8;
    NB[5] = 4 * 4 * 4;
    NB[6] = 2 * 2 * 2;
    const int Cin1[7]  = {3, 64, 96, 128, 160, 192, 224};
    const int Cout1[7] = {64, 96, 128, 160, 192, 224, 256};

    // MMA-path layers (indices 2..7 == L1c1..L3c2)
    const int LCin[8]  = {3, 64, 64, 96, 96, 128, 128, 160};
    const int LCinP[8] = {64, 64, 64, 128, 128, 128, 128, 192};
    const int LCout[8] = {64, 64, 96, 96, 128, 128, 160, 160};
    size_t woff[9];
    woff[0] = 0;
    for (int i = 0; i < 8; i++)
        woff[i + 1] = woff[i] + (size_t)27 * (LCinP[i] / 64) * 2 * LCout[i] * 128;

    // ---- level-0 structure ----
    k_setn<<<1, 1>>>(n0);
    k_fill<<<ceildiv(GRID_CELLS, 256), 256>>>(gA, -1, GRID_CELLS);
    k_scatter0<<<ceildiv(n0, 256), 256>>>(coors, n0);

    int* linCur = lA;
    int* gridCur = gA;
    int* linNxt = lB;
    int* gridNxt = gB;

    // ---- L0: pairs, scalar conv1 + conv2 (fp32, neighbor skipping) ----
    k_pairs<<<ceildiv(NB[0], 256), 256>>>(linCur, gridCur, pn, S[0]);
    k_conv0<<<ceildiv(NB[0], 4), 256>>>(feat_in, w[0], fA, pn);

    // weight blob for MMA layers 2..7
    for (int i = 2; i < 8; i++) {
        int total = 27 * LCinP[i] * LCout[i];
        k_wcvt<<<ceildiv(total, 256), 256>>>(w[i], wblob + woff[i],
                                             LCin[i], LCinP[i], LCout[i]);
    }

    k_conv1s<<<ceildiv(NB[0], 64), 256>>>(fA, w[1], fB, pn);

    // pool0: fB -> fA (fp32) + bh1/bl1 split (CP = LCinP[2] = 64)
    {
        int Sc = S[0] >> 1, P = Sc * Sc * Sc, nb = ceildiv(P, 1024);
        k_flags<<<ceildiv(P, 256), 256>>>(gridCur, S[0]);
        k_scanA<<<nb, 256>>>(P);
        k_scanB<<<1, 256>>>(nb, 1);
        k_scanC<<<nb, 256>>>(gridNxt, linNxt, P);
        k_pool2<<<NB[1], 64>>>(fB, fA, bh1, bl1, gridCur, linNxt, pn + 1, S[0], 64, 64);
        int* t;
        t = linCur; linCur = linNxt; linNxt = t;
        t = gridCur; gridCur = gridNxt; gridNxt = t;
    }

    // ---- MMA levels 1..3 ----
    for (int L = 1; L < 4; L++) {
        const int* np = pn + L;
        k_pairs<<<ceildiv(NB[L], 256), 256>>>(linCur, gridCur, np, S[L]);

        int li1 = 2 * L, li2 = 2 * L + 1;
        int gy = (L == 3) ? 5 : 1;
        launch_wconv(bh1, bl1, wblob + woff[li1], nullptr, bh2, bl2, LCinP[li2],
                     np, LCinP[li1], LCout[li1], NB[L], gy);
        launch_wconv(bh2, bl2, wblob + woff[li2], fB, nullptr, nullptr, 0,
                     np, LCinP[li2], LCout[li2], NB[L], gy);

        {
            int Sc = S[L] >> 1, P = Sc * Sc * Sc, nb = ceildiv(P, 1024);
            k_flags<<<ceildiv(P, 256), 256>>>(gridCur, S[L]);
            k_scanA<<<nb, 256>>>(P);
            k_scanB<<<1, 256>>>(nb, L + 1);
            k_scanC<<<nb, 256>>>(gridNxt, linNxt, P);
            int C = LCout[li2];
            int CP = (L < 3) ? pad64(C) : 0;
            int thr = CP ? CP : C;
            k_pool2<<<NB[L + 1], thr>>>(fB, fA, bh1, bl1, gridCur, linNxt,
                                        pn + L + 1, S[L], C, CP);
        }
        int* t;
        t = linCur; linCur = linNxt; linNxt = t;
        t = gridCur; gridCur = gridNxt; gridNxt = t;
    }

    // ---- FFMA levels 4..6 (pool L3 output in fA) ----
    const float* cur = fA;
    for (int L = 4; L < 7; L++) {
        const int* np = pn + L;
        k_pairs<<<ceildiv(NB[L], 256), 256>>>(linCur, gridCur, np, S[L]);
        int ci1 = Cin1[L], co1 = Cout1[L];
        float* o1 = (cur == fA) ? fB : fA;
        {
            dim3 g(ceildiv(NB[L], 16), co1 / 32), b(256);
            k_conv_small<<<g, b>>>(cur, w[2 * L], o1, np, ci1, co1);
        }
        float* o2 = (L == 6) ? (float*)d_out : ((o1 == fA) ? fB : fA);
        {
            dim3 g(ceildiv(NB[L], 16), co1 / 32), b(256);
            k_conv_small<<<g, b>>>(o1, w[2 * L + 1], o2, np, co1, co1);
        }
        cur = o2;
        if (L < 6) {
            int Sc = S[L] >> 1, P = Sc * Sc * Sc, nb = ceildiv(P, 1024);
            k_flags<<<ceildiv(P, 256), 256>>>(gridCur, S[L]);
            k_scanA<<<nb, 256>>>(P);
            k_scanB<<<1, 256>>>(nb, L + 1);
            k_scanC<<<nb, 256>>>(gridNxt, linNxt, P);
            float* po = (cur == fA) ? fB : fA;
            k_pool2<<<NB[L + 1], co1>>>(cur, po, nullptr, nullptr, gridCur, linNxt,
                                        pn + L + 1, S[L], co1, 0);
            cur = po;
            int* t;
            t = linCur; linCur = linNxt; linNxt = t;
            t = gridCur; gridCur = gridNxt; gridNxt = t;
        }
    }
}

// round 11
// speedup vs baseline: 1.0646x; 1.0177x over previous
#include <cuda_runtime.h>
#include <cuda_bf16.h>
#include <cstdint>

// ---------------------------------------------------------------------------
// Sparse submanifold 3D conv backbone, batch=1, 128^3 -> 2^3.
// L0 conv1+conv2 (density 4.8%): neighbor-skipping scalar fp32 kernels.
// L1..L3: mma.sync bf16x3 split-fp32. 64-row tiles, 256 threads, 2+ blocks/SM
// (independent barrier domains hide the per-stage convoy stalls).
// Levels 4-6 (n <= 512): scalar FFMA path.
// ---------------------------------------------------------------------------

#define NMAX 100000
#define GRID_CELLS (1 << 21)
#define FLAGS_MAX (1 << 18)

__device__ int   g_n[8];
__device__ int   g_linA[NMAX];
__device__ int   g_linB[NMAX];
__device__ int   g_gridA[GRID_CELLS];
__device__ int   g_gridB[GRID_CELLS];
__device__ int   g_pairs[27 * NMAX];
__device__ int   g_flags[FLAGS_MAX];
__device__ int   g_bsums[256];
__device__ __align__(1024) float g_featA[10000000];
__device__ __align__(1024) float g_featB[10000000];
// bf16 hi/lo feature tables: pair-1 = conv1 input, pair-2 = conv2 input
__device__ __align__(1024) __nv_bfloat16 g_bh1[12000000];
__device__ __align__(1024) __nv_bfloat16 g_bl1[12000000];
__device__ __align__(1024) __nv_bfloat16 g_bh2[12000000];
__device__ __align__(1024) __nv_bfloat16 g_bl2[12000000];
// pre-swizzled, transposed, split weight blob (layers 2..7)
__device__ __align__(1024) unsigned char g_wblob[16 * 1024 * 1024];

// ---------------------------------------------------------------------------

__device__ __forceinline__ void cp_async16(uint32_t dst, const void* src, int srcBytes) {
    asm volatile("cp.async.cg.shared.global [%0], [%1], 16, %2;\n"
                 :: "r"(dst), "l"(src), "r"(srcBytes));
}
__device__ __forceinline__ void cp_commit() {
    asm volatile("cp.async.commit_group;\n");
}
__device__ __forceinline__ uint32_t smem_u32(const void* p) {
    uint32_t a;
    asm("{ .reg .u64 t; cvta.to.shared.u64 t, %1; cvt.u32.u64 %0, t; }" : "=r"(a) : "l"(p));
    return a;
}
__device__ __forceinline__ void ldsm4(uint32_t* r, uint32_t addr) {
    asm volatile("ldmatrix.sync.aligned.m8n8.x4.shared.b16 {%0,%1,%2,%3}, [%4];"
                 : "=r"(r[0]), "=r"(r[1]), "=r"(r[2]), "=r"(r[3]) : "r"(addr));
}
__device__ __forceinline__ void ldsm2(uint32_t* r, uint32_t addr) {
    asm volatile("ldmatrix.sync.aligned.m8n8.x2.shared.b16 {%0,%1}, [%2];"
                 : "=r"(r[0]), "=r"(r[1]) : "r"(addr));
}
__device__ __forceinline__ void mma16816(float* d, const uint32_t* a, const uint32_t* b) {
    asm volatile("mma.sync.aligned.m16n8k16.row.col.f32.bf16.bf16.f32 "
                 "{%0,%1,%2,%3}, {%4,%5,%6,%7}, {%8,%9}, {%0,%1,%2,%3};"
                 : "+f"(d[0]), "+f"(d[1]), "+f"(d[2]), "+f"(d[3])
                 : "r"(a[0]), "r"(a[1]), "r"(a[2]), "r"(a[3]), "r"(b[0]), "r"(b[1]));
}

// ---------------------------------------------------------------------------

__global__ void k_setn(int n0) { g_n[0] = n0; }

__global__ void k_fill(int* g, int v, int P) {
    int i = blockIdx.x * blockDim.x + threadIdx.x;
    if (i < P) g[i] = v;
}

__global__ void k_scatter0(const int* __restrict__ coors, int n0) {
    int i = blockIdx.x * blockDim.x + threadIdx.x;
    if (i >= n0) return;
    int z = coors[i * 4 + 1];
    int y = coors[i * 4 + 2];
    int x = coors[i * 4 + 3];
    int l = (z * 128 + y) * 128 + x;
    g_linA[i] = l;
    g_gridA[l] = i;
}

__global__ void k_pairs(const int* __restrict__ lin, const int* __restrict__ grid,
                        const int* __restrict__ np, int S) {
    int n = *np;
    int i = blockIdx.x * blockDim.x + threadIdx.x;
    if (i >= n) return;
    int l = lin[i];
    int z = l / (S * S);
    int rem = l - z * S * S;
    int y = rem / S;
    int x = rem - y * S;
    int k = 0;
    #pragma unroll
    for (int dz = -1; dz <= 1; dz++)
        #pragma unroll
        for (int dy = -1; dy <= 1; dy++)
            #pragma unroll
            for (int dx = -1; dx <= 1; dx++) {
                int zz = z + dz, yy = y + dy, xx = x + dx;
                int v = -1;
                if (zz >= 0 && zz < S && yy >= 0 && yy < S && xx >= 0 && xx < S)
                    v = grid[(zz * S + yy) * S + xx];
                g_pairs[k * NMAX + i] = v;
                k++;
            }
}

// Weight blob: W[27,Cin,Cout] fp32 -> per-stage SW128 images of W^T
// [Cout rows x 64 cols] bf16, hi then lo. Stage = (k, ci-chunk).
__global__ void k_wcvt(const float* __restrict__ W, unsigned char* __restrict__ blob,
                       int Cin, int CinP, int Cout) {
    int total = 27 * CinP * Cout;
    int idx = blockIdx.x * 256 + threadIdx.x;
    if (idx >= total) return;
    int ci = idx % CinP;
    int t = idx / CinP;
    int co = t % Cout;
    int k = t / Cout;
    float v = (ci < Cin) ? W[((size_t)k * Cin + ci) * Cout + co] : 0.f;
    __nv_bfloat16 h = __float2bfloat16_rn(v);
    __nv_bfloat16 l = __float2bfloat16_rn(v - __bfloat162float(h));
    int ch = ci >> 6, cic = ci & 63;
    int sw = (((cic >> 3) ^ (co & 7)) << 4) + (cic & 7) * 2;
    int NCH = CinP >> 6;
    size_t stageBase = (size_t)(k * NCH + ch) * (2 * Cout * 128);
    *(__nv_bfloat16*)(blob + stageBase + (size_t)co * 128 + sw) = h;
    *(__nv_bfloat16*)(blob + stageBase + (size_t)Cout * 128 + (size_t)co * 128 + sw) = l;
}

// ---------------------------------------------------------------------------
// Fused L0 conv1: Cin=3, Cout=64, fp32 out, skips missing neighbors.
// ---------------------------------------------------------------------------
__global__ __launch_bounds__(256) void k_conv0(const float* __restrict__ feats,
                                               const float* __restrict__ W,
                                               float* __restrict__ out,
                                               const int* __restrict__ np) {
    __shared__ float Ws[27 * 3 * 64];
    int n = *np;
    int tid = threadIdx.x;
    for (int e = tid; e < 27 * 3 * 64; e += 256) Ws[e] = W[e];
    __syncthreads();
    int r = blockIdx.x * 4 + (tid >> 6);
    int lane = tid & 63;
    if (r >= n) return;
    float acc = 0.f;
    #pragma unroll 1
    for (int k = 0; k < 27; k++) {
        int id = g_pairs[k * NMAX + r];
        if (id >= 0) {
            float f0 = feats[id * 3 + 0];
            float f1 = feats[id * 3 + 1];
            float f2 = feats[id * 3 + 2];
            const float* wk = Ws + k * 192;
            acc += f0 * wk[lane] + f1 * wk[64 + lane] + f2 * wk[128 + lane];
        }
    }
    out[(size_t)r * 64 + lane] = acc;
}

// ---------------------------------------------------------------------------
// L0 conv2: Cin=64, Cout=64, fp32, neighbor-skipping (density ~4.8%).
// ---------------------------------------------------------------------------
__global__ __launch_bounds__(256) void k_conv1s(const float* __restrict__ fin,
                                                const float* __restrict__ W,
                                                float* __restrict__ out,
                                                const int* __restrict__ np) {
    __shared__ float Wt[64][68];
    int n = *np;
    int tid = threadIdx.x;
    int rr = tid >> 6;
    int c  = tid & 63;
    int rowBase = blockIdx.x * 64;
    if (rowBase >= n) return;

    float acc[16];
    #pragma unroll
    for (int i = 0; i < 16; i++) acc[i] = 0.f;

    for (int k = 0; k < 27; k++) {
        __syncthreads();
        for (int e = tid; e < 4096; e += 256) {
            int ci = e >> 6, co = e & 63;
            Wt[co][ci] = W[k * 4096 + e];
        }
        __syncthreads();
        #pragma unroll 1
        for (int i = 0; i < 16; i++) {
            int r = rowBase + rr * 16 + i;
            if (r >= n) break;
            int id = g_pairs[k * NMAX + r];
            if (id < 0) continue;
            const float4* f4 = (const float4*)(fin + (size_t)id * 64);
            const float4* w4 = (const float4*)&Wt[c][0];
            float s = 0.f;
            #pragma unroll
            for (int q = 0; q < 16; q++) {
                float4 fv = f4[q];
                float4 wv = w4[q];
                s += fv.x * wv.x + fv.y * wv.y + fv.z * wv.z + fv.w * wv.w;
            }
            acc[i] += s;
        }
    }
    #pragma unroll
    for (int i = 0; i < 16; i++) {
        int r = rowBase + rr * 16 + i;
        if (r < n) out[(size_t)r * 64 + c] = acc[i];
    }
}

// ---------------------------------------------------------------------------
// mma.sync conv: 64-row tile x CoutS col slice, bf16x3 split fp32.
// 256 threads = 8 warps = 4 row-groups x 2 col-halves.
// 2-stage cp.async pipeline. smem <= ~96KB -> 2+ blocks per SM.
// ---------------------------------------------------------------------------
template <int NT>   // NT = CoutS/8, divisible by 2
__global__ __launch_bounds__(256) void k_wconv(
    const __nv_bfloat16* __restrict__ bhi, const __nv_bfloat16* __restrict__ blo,
    const unsigned char* __restrict__ wblob,
    float* __restrict__ outF,
    __nv_bfloat16* __restrict__ outH, __nv_bfloat16* __restrict__ outL, int CP,
    const int* __restrict__ np, int CinP, int CoutF)
{
    const int NT2 = NT / 2;
    const int CoutS = NT * 8;
    const int WstageS = 2 * CoutS * 128;
    int n = *np;
    int rowBase = blockIdx.x * 64;
    if (rowBase >= n) return;
    int colBase = blockIdx.y * CoutS;

    extern __shared__ __align__(1024) unsigned char sm[];
    const uint32_t Asm = smem_u32(sm);
    const uint32_t Wsm = Asm + 2 * 16384;

    int tid = threadIdx.x;
    int wid = tid >> 5;
    int lane = tid & 31;

    const int NCH = CinP >> 6;
    const int S = 27 * NCH;
    const int WstageF = 2 * CoutF * 128;

    // A-gather roles: 4 threads per row: atile (hi/lo) x ahalf (64B half)
    int am = tid >> 2;         // 0..63 row in tile
    int sub = tid & 3;
    int atile = sub >> 1;
    int ahalf = sub & 1;
    const __nv_bfloat16* Asrc = atile ? blo : bhi;
    int r_g = rowBase + am;
    int curK = -1, curId = -1;

    float acc[NT2][4];
    #pragma unroll
    for (int j = 0; j < NT2; j++)
        #pragma unroll
        for (int q = 0; q < 4; q++) acc[j][q] = 0.f;

    auto load = [&](int buf, int s) {
        int k = s / NCH;
        int ch = s - k * NCH;
        if (k != curK) {
            curK = k;
            curId = (r_g < n) ? g_pairs[k * NMAX + r_g] : -1;
        }
        {
            const unsigned char* src =
                (const unsigned char*)(Asrc + (size_t)(curId < 0 ? 0 : curId) * CinP + ch * 64)
                + ahalf * 64;
            uint32_t dst = Asm + buf * 16384 + atile * 8192 + am * 128;
            int m7 = (am & 7) << 4;
            int sz = (curId >= 0) ? 16 : 0;
            #pragma unroll
            for (int c = 0; c < 4; c++) {
                int off = ahalf * 64 + c * 16;
                cp_async16(dst + (off ^ m7), src + c * 16, sz);
            }
        }
        {
            const unsigned char* src = wblob + (size_t)s * WstageF;
            const int hc = (CoutS * 128) >> 4;
            uint32_t dst = Wsm + buf * WstageS;
            for (int e = tid; e < 2 * hc; e += 256) {
                int half = (e >= hc) ? 1 : 0;
                int e2 = e - half * hc;
                const unsigned char* sp =
                    src + (size_t)((half ? (CoutF + colBase) : colBase)) * 128 + e2 * 16;
                cp_async16(dst + e * 16, sp, 16);
            }
        }
        cp_commit();
    };

    int rw = wid & 3;          // row group: rows rw*16 .. rw*16+15
    int cw = wid >> 2;         // col half
    int arow0 = rw * 16 + (lane & 15);
    int ac16 = (lane >> 4) & 1;
    int brow_l = lane & 7;
    int bc16 = (lane >> 3) & 1;

    load(0, 0);
    for (int s = 0; s < S; s++) {
        int b = s & 1;
        if (s + 1 < S) {
            load(b ^ 1, s + 1);
            asm volatile("cp.async.wait_group 1;\n");
        } else {
            asm volatile("cp.async.wait_group 0;\n");
        }
        __syncthreads();

        uint32_t AhB = Asm + b * 16384;
        uint32_t AlB = AhB + 8192;
        uint32_t WhB = Wsm + b * WstageS;
        uint32_t WlB = WhB + CoutS * 128;

        #pragma unroll
        for (int chunk = 0; chunk < 4; chunk++) {
            uint32_t ah[4], al[4];
            {
                uint32_t off = (uint32_t)arow0 * 128 + chunk * 32 + ac16 * 16;
                off ^= (off >> 3) & 0x70;
                ldsm4(ah, AhB + off);
                ldsm4(al, AlB + off);
            }
            #pragma unroll
            for (int j = 0; j < NT2; j++) {
                uint32_t off = (uint32_t)(cw * (NT2 * 8) + j * 8 + brow_l) * 128
                             + chunk * 32 + bc16 * 16;
                off ^= (off >> 3) & 0x70;
                uint32_t bh[2], bl[2];
                ldsm2(bh, WhB + off);
                ldsm2(bl, WlB + off);
                mma16816(acc[j], ah, bh);
                mma16816(acc[j], ah, bl);
                mma16816(acc[j], al, bh);
            }
        }
        __syncthreads();
    }

    int grp = lane >> 2, tg = lane & 3;
    int r0 = rowBase + rw * 16 + grp;
    #pragma unroll
    for (int half = 0; half < 2; half++) {
        int r = r0 + half * 8;
        if (r >= n) continue;
        #pragma unroll
        for (int j = 0; j < NT2; j++) {
            float d0 = acc[j][half * 2 + 0];
            float d1 = acc[j][half * 2 + 1];
            int c = colBase + cw * (NT2 * 8) + j * 8 + tg * 2;
            if (outF) {
                float2 v; v.x = d0; v.y = d1;
                *(float2*)(outF + (size_t)r * CoutF + c) = v;
            }
            if (outH) {
                __nv_bfloat16 h0 = __float2bfloat16_rn(d0);
                __nv_bfloat16 h1 = __float2bfloat16_rn(d1);
                __nv_bfloat16 l0 = __float2bfloat16_rn(d0 - __bfloat162float(h0));
                __nv_bfloat16 l1 = __float2bfloat16_rn(d1 - __bfloat162float(h1));
                uint32_t hp = ((uint32_t)(*(unsigned short*)&h1) << 16)
                            | (uint32_t)(*(unsigned short*)&h0);
                uint32_t lp = ((uint32_t)(*(unsigned short*)&l1) << 16)
                            | (uint32_t)(*(unsigned short*)&l0);
                *(uint32_t*)(outH + (size_t)r * CP + c) = hp;
                *(uint32_t*)(outL + (size_t)r * CP + c) = lp;
            }
        }
        if (outH && blockIdx.y == 0 && cw == 0) {
            for (int c = CoutF + tg * 2; c < CP; c += 8) {
                *(uint32_t*)(outH + (size_t)r * CP + c) = 0u;
                *(uint32_t*)(outL + (size_t)r * CP + c) = 0u;
            }
        }
    }
}

// ---------------------------------------------------------------------------
// Small-level scalar conv (n <= 512): 16 rows x 32 cols per block.
// ---------------------------------------------------------------------------
__global__ __launch_bounds__(256) void k_conv_small(const float* __restrict__ feats,
                                                    const float* __restrict__ W,
                                                    float* __restrict__ out,
                                                    const int* __restrict__ np,
                                                    int Cin, int Cout) {
    int n = *np;
    int rowBase = blockIdx.x * 16;
    if (rowBase >= n) return;
    int colBase = blockIdx.y * 32;

    __shared__ float As[16][33];
    __shared__ float Ws[32][33];

    int tid = threadIdx.x;
    int tm = tid >> 5;
    int tn = tid & 31;

    float acc0 = 0.f, acc1 = 0.f;

    for (int k = 0; k < 27; k++) {
        for (int c0 = 0; c0 < Cin; c0 += 32) {
            __syncthreads();
            {
                int e = tid;
                #pragma unroll
                for (int j = 0; j < 2; j++, e += 256) {
                    int m = e >> 5, c = e & 31;
                    int r = rowBase + m;
                    int id = (r < n) ? g_pairs[k * NMAX + r] : -1;
                    As[m][c] = (id >= 0) ? feats[(size_t)id * Cin + c0 + c] : 0.f;
                }
            }
            {
                const float* Wk = W + ((size_t)k * Cin + c0) * Cout + colBase;
                int e = tid;
                #pragma unroll
                for (int j = 0; j < 4; j++, e += 256) {
                    int kk = e >> 5, c = e & 31;
                    Ws[kk][c] = Wk[(size_t)kk * Cout + c];
                }
            }
            __syncthreads();
            #pragma unroll 8
            for (int kk = 0; kk < 32; kk++) {
                float w = Ws[kk][tn];
                acc0 += As[tm * 2][kk] * w;
                acc1 += As[tm * 2 + 1][kk] * w;
            }
        }
    }

    int r0 = rowBase + tm * 2;
    if (r0 < n)     out[(size_t)r0 * Cout + colBase + tn] = acc0;
    if (r0 + 1 < n) out[(size_t)(r0 + 1) * Cout + colBase + tn] = acc1;
}

// ---------------------------------------------------------------------------
// Pool structure kernels + pool with optional bf16 split output
// ---------------------------------------------------------------------------
__global__ void k_flags(const int* __restrict__ fineGrid, int S) {
    int Sc = S >> 1;
    int P = Sc * Sc * Sc;
    int p = blockIdx.x * blockDim.x + threadIdx.x;
    if (p >= P) return;
    int pz = p / (Sc * Sc);
    int rem = p - pz * Sc * Sc;
    int py = rem / Sc;
    int px = rem - py * Sc;
    int occ = 0;
    #pragma unroll
    for (int a = 0; a < 2; a++)
        #pragma unroll
        for (int b = 0; b < 2; b++)
            #pragma unroll
            for (int c = 0; c < 2; c++) {
                int l = ((2 * pz + a) * S + 2 * py + b) * S + 2 * px + c;
                if (fineGrid[l] >= 0) occ = 1;
            }
    g_flags[p] = occ;
}

__global__ void k_scanA(int P) {
    __shared__ int sh[256];
    int t = threadIdx.x;
    int base = blockIdx.x * 1024;
    int s = 0;
    #pragma unroll
    for (int j = 0; j < 4; j++) {
        int p = base + t * 4 + j;
        if (p < P) s += g_flags[p];
    }
    sh[t] = s;
    __syncthreads();
    for (int d = 128; d > 0; d >>= 1) {
        if (t < d) sh[t] += sh[t + d];
        __syncthreads();
    }
    if (t == 0) g_bsums[blockIdx.x] = sh[0];
}

__global__ void k_scanB(int nb, int Lnext) {
    __shared__ int sh[256];
    int t = threadIdx.x;
    int v = (t < nb) ? g_bsums[t] : 0;
    sh[t] = v;
    __syncthreads();
    for (int d = 1; d < 256; d <<= 1) {
        int x = (t >= d) ? sh[t - d] : 0;
        __syncthreads();
        sh[t] += x;
        __syncthreads();
    }
    if (t < nb) g_bsums[t] = sh[t] - v;
    if (t == 255) g_n[Lnext] = sh[255];
}

__global__ void k_scanC(int* __restrict__ coarseGrid, int* __restrict__ linNext, int P) {
    __shared__ int sh[256];
    int t = threadIdx.x;
    int base = blockIdx.x * 1024;
    int f[4];
    int s = 0;
    #pragma unroll
    for (int j = 0; j < 4; j++) {
        int p = base + t * 4 + j;
        f[j] = (p < P) ? g_flags[p] : 0;
        s += f[j];
    }
    int v = s;
    sh[t] = v;
    __syncthreads();
    for (int d = 1; d < 256; d <<= 1) {
        int x = (t >= d) ? sh[t - d] : 0;
        __syncthreads();
        sh[t] += x;
        __syncthreads();
    }
    int off = g_bsums[blockIdx.x] + sh[t] - v;
    #pragma unroll
    for (int j = 0; j < 4; j++) {
        int p = base + t * 4 + j;
        if (p >= P) break;
        if (f[j]) {
            coarseGrid[p] = off;
            linNext[off] = p;
            off++;
        } else {
            coarseGrid[p] = -1;
        }
    }
}

__global__ void k_pool2(const float* __restrict__ feats, float* __restrict__ out,
                        __nv_bfloat16* __restrict__ oh, __nv_bfloat16* __restrict__ ol,
                        const int* __restrict__ fineGrid, const int* __restrict__ linNext,
                        const int* __restrict__ np, int S, int C, int CP) {
    int row = blockIdx.x;
    if (row >= *np) return;
    int Sc = S >> 1;
    int p = linNext[row];
    int pz = p / (Sc * Sc);
    int rem = p - pz * Sc * Sc;
    int py = rem / Sc;
    int px = rem - py * Sc;
    int c = threadIdx.x;
    if (c < C) {
        float m = -3.4e38f;
        #pragma unroll
        for (int a = 0; a < 2; a++)
            #pragma unroll
            for (int b = 0; b < 2; b++)
                #pragma unroll
                for (int d = 0; d < 2; d++) {
                    int l = ((2 * pz + a) * S + 2 * py + b) * S + 2 * px + d;
                    int r = fineGrid[l];
                    if (r >= 0) m = fmaxf(m, feats[(size_t)r * C + c]);
                }
        out[(size_t)row * C + c] = m;
        if (CP) {
            __nv_bfloat16 h = __float2bfloat16_rn(m);
            oh[(size_t)row * CP + c] = h;
            ol[(size_t)row * CP + c] = __float2bfloat16_rn(m - __bfloat162float(h));
        }
    } else if (CP && c < CP) {
        oh[(size_t)row * CP + c] = __float2bfloat16_rn(0.f);
        ol[(size_t)row * CP + c] = __float2bfloat16_rn(0.f);
    }
}

// ---------------------------------------------------------------------------

static inline int ceildiv(int a, int b) { return (a + b - 1) / b; }
static inline int pad64(int c) { return (c + 63) & ~63; }

static void launch_wconv(const __nv_bfloat16* bhi, const __nv_bfloat16* blo,
                         const unsigned char* wb, float* outF,
                         __nv_bfloat16* oh, __nv_bfloat16* ol, int CP,
                         const int* np, int CinP, int Cout, int nBound, int gy) {
    int CoutS = Cout / gy;
    int NT = CoutS / 8;
    dim3 g(ceildiv(nBound, 64), gy), b(256);
    int smem = 2 * 16384 + 2 * 2 * CoutS * 128;
    switch (NT) {
        case 4:
            cudaFuncSetAttribute(k_wconv<4>, cudaFuncAttributeMaxDynamicSharedMemorySize, smem);
            k_wconv<4><<<g, b, smem>>>(bhi, blo, wb, outF, oh, ol, CP, np, CinP, Cout);
            break;
        case 8:
            cudaFuncSetAttribute(k_wconv<8>, cudaFuncAttributeMaxDynamicSharedMemorySize, smem);
            k_wconv<8><<<g, b, smem>>>(bhi, blo, wb, outF, oh, ol, CP, np, CinP, Cout);
            break;
        case 12:
            cudaFuncSetAttribute(k_wconv<12>, cudaFuncAttributeMaxDynamicSharedMemorySize, smem);
            k_wconv<12><<<g, b, smem>>>(bhi, blo, wb, outF, oh, ol, CP, np, CinP, Cout);
            break;
        case 16:
            cudaFuncSetAttribute(k_wconv<16>, cudaFuncAttributeMaxDynamicSharedMemorySize, smem);
            k_wconv<16><<<g, b, smem>>>(bhi, blo, wb, outF, oh, ol, CP, np, CinP, Cout);
            break;
    }
}

extern "C" void kernel_launch(void* const* d_in, const int* in_sizes, int n_in,
                              void* d_out, int out_size) {
    const float* feat_in = (const float*)d_in[0];
    const int*   coors   = (const int*)d_in[1];
    const float* w[14];
    for (int i = 0; i < 14; i++) w[i] = (const float*)d_in[3 + i];

    int n0 = in_sizes[0] / 3;

    float *fA, *fB;
    __nv_bfloat16 *bh1, *bl1, *bh2, *bl2;
    unsigned char* wblob;
    int *gA, *gB, *lA, *lB, *pn;
    cudaGetSymbolAddress((void**)&fA, g_featA);
    cudaGetSymbolAddress((void**)&fB, g_featB);
    cudaGetSymbolAddress((void**)&bh1, g_bh1);
    cudaGetSymbolAddress((void**)&bl1, g_bl1);
    cudaGetSymbolAddress((void**)&bh2, g_bh2);
    cudaGetSymbolAddress((void**)&bl2, g_bl2);
    cudaGetSymbolAddress((void**)&wblob, g_wblob);
    cudaGetSymbolAddress((void**)&gA, g_gridA);
    cudaGetSymbolAddress((void**)&gB, g_gridB);
    cudaGetSymbolAddress((void**)&lA, g_linA);
    cudaGetSymbolAddress((void**)&lB, g_linB);
    cudaGetSymbolAddress((void**)&pn, g_n);

    const int S[7]  = {128, 64, 32, 16, 8, 4, 2};
    int NB[7];
    NB[0] = n0;
    NB[1] = n0 < (64 * 64 * 64) ? n0 : (64 * 64 * 64);
    NB[2] = 32 * 32 * 32;
    NB[3] = 16 * 16 * 16;
    NB[4] = 8 * 8 * 8;
    NB[5] = 4 * 4 * 4;
    NB[6] = 2 * 2 * 2;
    const int Cin1[7]  = {3, 64, 96, 128, 160, 192, 224};
    const int Cout1[7] = {64, 96, 128, 160, 192, 224, 256};

    // MMA-path layers (indices 2..7 == L1c1..L3c2)
    const int LCin[8]  = {3, 64, 64, 96, 96, 128, 128, 160};
    const int LCinP[8] = {64, 64, 64, 128, 128, 128, 128, 192};
    const int LCout[8] = {64, 64, 96, 96, 128, 128, 160, 160};
    size_t woff[9];
    woff[0] = 0;
    for (int i = 0; i < 8; i++)
        woff[i + 1] = woff[i] + (size_t)27 * (LCinP[i] / 64) * 2 * LCout[i] * 128;

    // ---- level-0 structure ----
    k_setn<<<1, 1>>>(n0);
    k_fill<<<ceildiv(GRID_CELLS, 256), 256>>>(gA, -1, GRID_CELLS);
    k_scatter0<<<ceildiv(n0, 256), 256>>>(coors, n0);

    int* linCur = lA;
    int* gridCur = gA;
    int* linNxt = lB;
    int* gridNxt = gB;

    // ---- L0: pairs, scalar conv1 + conv2 (fp32, neighbor skipping) ----
    k_pairs<<<ceildiv(NB[0], 256), 256>>>(linCur, gridCur, pn, S[0]);
    k_conv0<<<ceildiv(NB[0], 4), 256>>>(feat_in, w[0], fA, pn);

    // weight blob for MMA layers 2..7
    for (int i = 2; i < 8; i++) {
        int total = 27 * LCinP[i] * LCout[i];
        k_wcvt<<<ceildiv(total, 256), 256>>>(w[i], wblob + woff[i],
                                             LCin[i], LCinP[i], LCout[i]);
    }

    k_conv1s<<<ceildiv(NB[0], 64), 256>>>(fA, w[1], fB, pn);

    // pool0: fB -> fA (fp32) + bh1/bl1 split (CP = LCinP[2] = 64)
    {
        int Sc = S[0] >> 1, P = Sc * Sc * Sc, nb = ceildiv(P, 1024);
        k_flags<<<ceildiv(P, 256), 256>>>(gridCur, S[0]);
        k_scanA<<<nb, 256>>>(P);
        k_scanB<<<1, 256>>>(nb, 1);
        k_scanC<<<nb, 256>>>(gridNxt, linNxt, P);
        k_pool2<<<NB[1], 64>>>(fB, fA, bh1, bl1, gridCur, linNxt, pn + 1, S[0], 64, 64);
        int* t;
        t = linCur; linCur = linNxt; linNxt = t;
        t = gridCur; gridCur = gridNxt; gridNxt = t;
    }

    // ---- MMA levels 1..3 ----
    for (int L = 1; L < 4; L++) {
        const int* np = pn + L;
        k_pairs<<<ceildiv(NB[L], 256), 256>>>(linCur, gridCur, np, S[L]);

        int li1 = 2 * L, li2 = 2 * L + 1;
        int gy = (L == 3) ? 5 : 1;
        launch_wconv(bh1, bl1, wblob + woff[li1], nullptr, bh2, bl2, LCinP[li2],
                     np, LCinP[li1], LCout[li1], NB[L], gy);
        launch_wconv(bh2, bl2, wblob + woff[li2], fB, nullptr, nullptr, 0,
                     np, LCinP[li2], LCout[li2], NB[L], gy);

        {
            int Sc = S[L] >> 1, P = Sc * Sc * Sc, nb = ceildiv(P, 1024);
            k_flags<<<ceildiv(P, 256), 256>>>(gridCur, S[L]);
            k_scanA<<<nb, 256>>>(P);
            k_scanB<<<1, 256>>>(nb, L + 1);
            k_scanC<<<nb, 256>>>(gridNxt, linNxt, P);
            int C = LCout[li2];
            int CP = (L < 3) ? pad64(C) : 0;
            int thr = CP ? CP : C;
            k_pool2<<<NB[L + 1], thr>>>(fB, fA, bh1, bl1, gridCur, linNxt,
                                        pn + L + 1, S[L], C, CP);
        }
        int* t;
        t = linCur; linCur = linNxt; linNxt = t;
        t = gridCur; gridCur = gridNxt; gridNxt = t;
    }

    // ---- FFMA levels 4..6 (pool L3 output in fA) ----
    const float* cur = fA;
    for (int L = 4; L < 7; L++) {
        const int* np = pn + L;
        k_pairs<<<ceildiv(NB[L], 256), 256>>>(linCur, gridCur, np, S[L]);
        int ci1 = Cin1[L], co1 = Cout1[L];
        float* o1 = (cur == fA) ? fB : fA;
        {
            dim3 g(ceildiv(NB[L], 16), co1 / 32), b(256);
            k_conv_small<<<g, b>>>(cur, w[2 * L], o1, np, ci1, co1);
        }
        float* o2 = (L == 6) ? (float*)d_out : ((o1 == fA) ? fB : fA);
        {
            dim3 g(ceildiv(NB[L], 16), co1 / 32), b(256);
            k_conv_small<<<g, b>>>(o1, w[2 * L + 1], o2, np, co1, co1);
        }
        cur = o2;
        if (L < 6) {
            int Sc = S[L] >> 1, P = Sc * Sc * Sc, nb = ceildiv(P, 1024);
            k_flags<<<ceildiv(P, 256), 256>>>(gridCur, S[L]);
            k_scanA<<<nb, 256>>>(P);
            k_scanB<<<1, 256>>>(nb, L + 1);
            k_scanC<<<nb, 256>>>(gridNxt, linNxt, P);
            float* po = (cur == fA) ? fB : fA;
            k_pool2<<<NB[L + 1], co1>>>(cur, po, nullptr, nullptr, gridCur, linNxt,
                                        pn + L + 1, S[L], co1, 0);
            cur = po;
            int* t;
            t = linCur; linCur = linNxt; linNxt = t;
            t = gridCur; gridCur = gridNxt; gridNxt = t;
        }
    }
}

// round 12
// speedup vs baseline: 1.3109x; 1.2313x over previous
#include <cuda_runtime.h>
#include <cuda_fp16.h>
#include <cstdint>

// ---------------------------------------------------------------------------
// Sparse submanifold 3D conv backbone, batch=1, 128^3 -> 2^3.
// L0 conv1 (Cin=3): neighbor-skipping scalar, writes fp16 feature table.
// L0c2..L3: mma.sync fp16 2-term split (A fp16, W 2-limb fp16, W pre-scaled
// by 256 to keep Wlo normal; epilogue multiplies by 1/256).
// Levels 4-6 (n <= 512): scalar FFMA path.
// ---------------------------------------------------------------------------

#define NMAX 100000
#define GRID_CELLS (1 << 21)
#define FLAGS_MAX (1 << 18)

__device__ int   g_n[8];
__device__ int   g_linA[NMAX];
__device__ int   g_linB[NMAX];
__device__ int   g_gridA[GRID_CELLS];
__device__ int   g_gridB[GRID_CELLS];
__device__ int   g_pairs[27 * NMAX];
__device__ int   g_flags[FLAGS_MAX];
__device__ int   g_bsums[256];
__device__ __align__(1024) float g_featA[10000000];
__device__ __align__(1024) float g_featB[10000000];
// fp16 feature tables: t1 = conv1 input, t2 = conv2 input
__device__ __align__(1024) __half g_fh1[12000000];
__device__ __align__(1024) __half g_fh2[12000000];
// pre-swizzled, transposed, 2-limb fp16 weight blob (layers 1..7), scaled x256
__device__ __align__(1024) unsigned char g_wblob[16 * 1024 * 1024];

#define WSCALE 256.0f
#define WISCALE 0.00390625f

// ---------------------------------------------------------------------------

__device__ __forceinline__ void cp_async16(uint32_t dst, const void* src, int srcBytes) {
    asm volatile("cp.async.cg.shared.global [%0], [%1], 16, %2;\n"
                 :: "r"(dst), "l"(src), "r"(srcBytes));
}
__device__ __forceinline__ void cp_commit() {
    asm volatile("cp.async.commit_group;\n");
}
__device__ __forceinline__ uint32_t smem_u32(const void* p) {
    uint32_t a;
    asm("{ .reg .u64 t; cvta.to.shared.u64 t, %1; cvt.u32.u64 %0, t; }" : "=r"(a) : "l"(p));
    return a;
}
__device__ __forceinline__ void ldsm4(uint32_t* r, uint32_t addr) {
    asm volatile("ldmatrix.sync.aligned.m8n8.x4.shared.b16 {%0,%1,%2,%3}, [%4];"
                 : "=r"(r[0]), "=r"(r[1]), "=r"(r[2]), "=r"(r[3]) : "r"(addr));
}
__device__ __forceinline__ void ldsm2(uint32_t* r, uint32_t addr) {
    asm volatile("ldmatrix.sync.aligned.m8n8.x2.shared.b16 {%0,%1}, [%2];"
                 : "=r"(r[0]), "=r"(r[1]) : "r"(addr));
}
__device__ __forceinline__ void mma16816(float* d, const uint32_t* a, const uint32_t* b) {
    asm volatile("mma.sync.aligned.m16n8k16.row.col.f32.f16.f16.f32 "
                 "{%0,%1,%2,%3}, {%4,%5,%6,%7}, {%8,%9}, {%0,%1,%2,%3};"
                 : "+f"(d[0]), "+f"(d[1]), "+f"(d[2]), "+f"(d[3])
                 : "r"(a[0]), "r"(a[1]), "r"(a[2]), "r"(a[3]), "r"(b[0]), "r"(b[1]));
}

// ---------------------------------------------------------------------------

__global__ void k_setn(int n0) { g_n[0] = n0; }

__global__ void k_fill(int* g, int v, int P) {
    int i = blockIdx.x * blockDim.x + threadIdx.x;
    if (i < P) g[i] = v;
}

__global__ void k_scatter0(const int* __restrict__ coors, int n0) {
    int i = blockIdx.x * blockDim.x + threadIdx.x;
    if (i >= n0) return;
    int z = coors[i * 4 + 1];
    int y = coors[i * 4 + 2];
    int x = coors[i * 4 + 3];
    int l = (z * 128 + y) * 128 + x;
    g_linA[i] = l;
    g_gridA[l] = i;
}

__global__ void k_pairs(const int* __restrict__ lin, const int* __restrict__ grid,
                        const int* __restrict__ np, int S) {
    int n = *np;
    int i = blockIdx.x * blockDim.x + threadIdx.x;
    if (i >= n) return;
    int l = lin[i];
    int z = l / (S * S);
    int rem = l - z * S * S;
    int y = rem / S;
    int x = rem - y * S;
    int k = 0;
    #pragma unroll
    for (int dz = -1; dz <= 1; dz++)
        #pragma unroll
        for (int dy = -1; dy <= 1; dy++)
            #pragma unroll
            for (int dx = -1; dx <= 1; dx++) {
                int zz = z + dz, yy = y + dy, xx = x + dx;
                int v = -1;
                if (zz >= 0 && zz < S && yy >= 0 && yy < S && xx >= 0 && xx < S)
                    v = grid[(zz * S + yy) * S + xx];
                g_pairs[k * NMAX + i] = v;
                k++;
            }
}

// Weight blob: W[27,Cin,Cout] fp32 -> per-stage SW128 images of W^T
// [Cout rows x 64 cols] fp16 (x256), hi then lo. Stage = (k, ci-chunk).
__global__ void k_wcvt(const float* __restrict__ W, unsigned char* __restrict__ blob,
                       int Cin, int CinP, int Cout) {
    int total = 27 * CinP * Cout;
    int idx = blockIdx.x * 256 + threadIdx.x;
    if (idx >= total) return;
    int ci = idx % CinP;
    int t = idx / CinP;
    int co = t % Cout;
    int k = t / Cout;
    float v = (ci < Cin) ? W[((size_t)k * Cin + ci) * Cout + co] * WSCALE : 0.f;
    __half h = __float2half_rn(v);
    __half l = __float2half_rn(v - __half2float(h));
    int ch = ci >> 6, cic = ci & 63;
    int sw = (((cic >> 3) ^ (co & 7)) << 4) + (cic & 7) * 2;
    int NCH = CinP >> 6;
    size_t stageBase = (size_t)(k * NCH + ch) * (2 * Cout * 128);
    *(__half*)(blob + stageBase + (size_t)co * 128 + sw) = h;
    *(__half*)(blob + stageBase + (size_t)Cout * 128 + (size_t)co * 128 + sw) = l;
}

// ---------------------------------------------------------------------------
// Fused L0 conv1: Cin=3, Cout=64, writes fp16 table (CP=64), skips missing.
// ---------------------------------------------------------------------------
__global__ __launch_bounds__(256) void k_conv0(const float* __restrict__ feats,
                                               const float* __restrict__ W,
                                               __half* __restrict__ out,
                                               const int* __restrict__ np) {
    __shared__ float Ws[27 * 3 * 64];
    int n = *np;
    int tid = threadIdx.x;
    for (int e = tid; e < 27 * 3 * 64; e += 256) Ws[e] = W[e];
    __syncthreads();
    int r = blockIdx.x * 4 + (tid >> 6);
    int lane = tid & 63;
    if (r >= n) return;
    float acc = 0.f;
    #pragma unroll 1
    for (int k = 0; k < 27; k++) {
        int id = g_pairs[k * NMAX + r];
        if (id >= 0) {
            float f0 = feats[id * 3 + 0];
            float f1 = feats[id * 3 + 1];
            float f2 = feats[id * 3 + 2];
            const float* wk = Ws + k * 192;
            acc += f0 * wk[lane] + f1 * wk[64 + lane] + f2 * wk[128 + lane];
        }
    }
    out[(size_t)r * 64 + lane] = __float2half_rn(acc);
}

// ---------------------------------------------------------------------------
// mma.sync conv: 128-row tile x CoutS col slice, fp16 2-term split.
// 512 threads = 16 warps = 4 row-groups x 4 col-quarters.
// 2-stage cp.async pipeline. A: single fp16 table. D = A*Whi + A*Wlo, /256.
// ---------------------------------------------------------------------------
template <int NT>   // NT = CoutS/8, divisible by 4
__global__ __launch_bounds__(512) void k_wconv(
    const __half* __restrict__ fin,
    const unsigned char* __restrict__ wblob,
    float* __restrict__ outF,
    __half* __restrict__ outH, int CP,
    const int* __restrict__ np, int CinP, int CoutF)
{
    const int NT4 = NT / 4;
    const int CoutS = NT * 8;
    const int WstageS = 2 * CoutS * 128;
    int n = *np;
    int rowBase = blockIdx.x * 128;
    if (rowBase >= n) return;
    int colBase = blockIdx.y * CoutS;

    extern __shared__ __align__(1024) unsigned char sm[];
    const uint32_t Asm = smem_u32(sm);        // 2 stages x 16KB
    const uint32_t Wsm = Asm + 2 * 16384;

    int tid = threadIdx.x;
    int wid = tid >> 5;
    int lane = tid & 31;

    const int NCH = CinP >> 6;
    const int S = 27 * NCH;
    const int WstageF = 2 * CoutF * 128;

    // A-gather: 4 threads per row, each loads 2 x 16B chunks
    int am = tid >> 2;        // 0..127 row
    int q = tid & 3;          // chunk group
    int r_g = rowBase + am;
    int curK = -1, curId = -1;

    float acc[2][NT4][4];
    #pragma unroll
    for (int mt = 0; mt < 2; mt++)
        #pragma unroll
        for (int j = 0; j < NT4; j++)
            #pragma unroll
            for (int p = 0; p < 4; p++) acc[mt][j][p] = 0.f;

    auto load = [&](int buf, int s) {
        int k = s / NCH;
        int ch = s - k * NCH;
        if (k != curK) {
            curK = k;
            curId = (r_g < n) ? g_pairs[k * NMAX + r_g] : -1;
        }
        {
            const unsigned char* src =
                (const unsigned char*)(fin + (size_t)(curId < 0 ? 0 : curId) * CinP + ch * 64);
            uint32_t dst = Asm + buf * 16384 + am * 128;
            int m7 = (am & 7) << 4;
            int sz = (curId >= 0) ? 16 : 0;
            #pragma unroll
            for (int c = q * 2; c < q * 2 + 2; c++)
                cp_async16(dst + ((c << 4) ^ m7), src + c * 16, sz);
        }
        {
            const unsigned char* src = wblob + (size_t)s * WstageF;
            const int hc = (CoutS * 128) >> 4;
            uint32_t dst = Wsm + buf * WstageS;
            for (int e = tid; e < 2 * hc; e += 512) {
                int half = (e >= hc) ? 1 : 0;
                int e2 = e - half * hc;
                const unsigned char* sp =
                    src + (size_t)((half ? (CoutF + colBase) : colBase)) * 128 + e2 * 16;
                cp_async16(dst + e * 16, sp, 16);
            }
        }
        cp_commit();
    };

    int rw = wid & 3;
    int cw = wid >> 2;
    int arow0 = rw * 32 + (lane & 15);
    int ac16 = (lane >> 4) & 1;
    int brow_l = lane & 7;
    int bc16 = (lane >> 3) & 1;

    load(0, 0);
    for (int s = 0; s < S; s++) {
        int b = s & 1;
        if (s + 1 < S) {
            load(b ^ 1, s + 1);
            asm volatile("cp.async.wait_group 1;\n");
        } else {
            asm volatile("cp.async.wait_group 0;\n");
        }
        __syncthreads();

        uint32_t AhB = Asm + b * 16384;
        uint32_t WhB = Wsm + b * WstageS;
        uint32_t WlB = WhB + CoutS * 128;

        #pragma unroll
        for (int chunk = 0; chunk < 4; chunk++) {
            uint32_t ah[2][4];
            #pragma unroll
            for (int mt = 0; mt < 2; mt++) {
                uint32_t off = (uint32_t)(arow0 + mt * 16) * 128 + chunk * 32 + ac16 * 16;
                off ^= (off >> 3) & 0x70;
                ldsm4(ah[mt], AhB + off);
            }
            #pragma unroll
            for (int j = 0; j < NT4; j++) {
                uint32_t off = (uint32_t)(cw * (NT4 * 8) + j * 8 + brow_l) * 128
                             + chunk * 32 + bc16 * 16;
                off ^= (off >> 3) & 0x70;
                uint32_t bh[2], bl[2];
                ldsm2(bh, WhB + off);
                ldsm2(bl, WlB + off);
                #pragma unroll
                for (int mt = 0; mt < 2; mt++) {
                    mma16816(acc[mt][j], ah[mt], bh);
                    mma16816(acc[mt][j], ah[mt], bl);
                }
            }
        }
        __syncthreads();
    }

    int grp = lane >> 2, tg = lane & 3;
    #pragma unroll
    for (int mt = 0; mt < 2; mt++) {
        int r0 = rowBase + rw * 32 + mt * 16 + grp;
        #pragma unroll
        for (int half = 0; half < 2; half++) {
            int r = r0 + half * 8;
            if (r >= n) continue;
            #pragma unroll
            for (int j = 0; j < NT4; j++) {
                float d0 = acc[mt][j][half * 2 + 0] * WISCALE;
                float d1 = acc[mt][j][half * 2 + 1] * WISCALE;
                int c = colBase + cw * (NT4 * 8) + j * 8 + tg * 2;
                if (outF) {
                    float2 v; v.x = d0; v.y = d1;
                    *(float2*)(outF + (size_t)r * CoutF + c) = v;
                }
                if (outH) {
                    __half h0 = __float2half_rn(d0);
                    __half h1 = __float2half_rn(d1);
                    uint32_t hp = ((uint32_t)(*(unsigned short*)&h1) << 16)
                                | (uint32_t)(*(unsigned short*)&h0);
                    *(uint32_t*)(outH + (size_t)r * CP + c) = hp;
                }
            }
            if (outH && blockIdx.y == 0 && cw == 0) {
                for (int c = CoutF + tg * 2; c < CP; c += 8)
                    *(uint32_t*)(outH + (size_t)r * CP + c) = 0u;
            }
        }
    }
}

// ---------------------------------------------------------------------------
// Small-level scalar conv (n <= 512): 16 rows x 32 cols per block.
// ---------------------------------------------------------------------------
__global__ __launch_bounds__(256) void k_conv_small(const float* __restrict__ feats,
                                                    const float* __restrict__ W,
                                                    float* __restrict__ out,
                                                    const int* __restrict__ np,
                                                    int Cin, int Cout) {
    int n = *np;
    int rowBase = blockIdx.x * 16;
    if (rowBase >= n) return;
    int colBase = blockIdx.y * 32;

    __shared__ float As[16][33];
    __shared__ float Ws[32][33];

    int tid = threadIdx.x;
    int tm = tid >> 5;
    int tn = tid & 31;

    float acc0 = 0.f, acc1 = 0.f;

    for (int k = 0; k < 27; k++) {
        for (int c0 = 0; c0 < Cin; c0 += 32) {
            __syncthreads();
            {
                int e = tid;
                #pragma unroll
                for (int j = 0; j < 2; j++, e += 256) {
                    int m = e >> 5, c = e & 31;
                    int r = rowBase + m;
                    int id = (r < n) ? g_pairs[k * NMAX + r] : -1;
                    As[m][c] = (id >= 0) ? feats[(size_t)id * Cin + c0 + c] : 0.f;
                }
            }
            {
                const float* Wk = W + ((size_t)k * Cin + c0) * Cout + colBase;
                int e = tid;
                #pragma unroll
                for (int j = 0; j < 4; j++, e += 256) {
                    int kk = e >> 5, c = e & 31;
                    Ws[kk][c] = Wk[(size_t)kk * Cout + c];
                }
            }
            __syncthreads();
            #pragma unroll 8
            for (int kk = 0; kk < 32; kk++) {
                float w = Ws[kk][tn];
                acc0 += As[tm * 2][kk] * w;
                acc1 += As[tm * 2 + 1][kk] * w;
            }
        }
    }

    int r0 = rowBase + tm * 2;
    if (r0 < n)     out[(size_t)r0 * Cout + colBase + tn] = acc0;
    if (r0 + 1 < n) out[(size_t)(r0 + 1) * Cout + colBase + tn] = acc1;
}

// ---------------------------------------------------------------------------
// Pool structure kernels + pool with optional fp16 output table
// ---------------------------------------------------------------------------
__global__ void k_flags(const int* __restrict__ fineGrid, int S) {
    int Sc = S >> 1;
    int P = Sc * Sc * Sc;
    int p = blockIdx.x * blockDim.x + threadIdx.x;
    if (p >= P) return;
    int pz = p / (Sc * Sc);
    int rem = p - pz * Sc * Sc;
    int py = rem / Sc;
    int px = rem - py * Sc;
    int occ = 0;
    #pragma unroll
    for (int a = 0; a < 2; a++)
        #pragma unroll
        for (int b = 0; b < 2; b++)
            #pragma unroll
            for (int c = 0; c < 2; c++) {
                int l = ((2 * pz + a) * S + 2 * py + b) * S + 2 * px + c;
                if (fineGrid[l] >= 0) occ = 1;
            }
    g_flags[p] = occ;
}

__global__ void k_scanA(int P) {
    __shared__ int sh[256];
    int t = threadIdx.x;
    int base = blockIdx.x * 1024;
    int s = 0;
    #pragma unroll
    for (int j = 0; j < 4; j++) {
        int p = base + t * 4 + j;
        if (p < P) s += g_flags[p];
    }
    sh[t] = s;
    __syncthreads();
    for (int d = 128; d > 0; d >>= 1) {
        if (t < d) sh[t] += sh[t + d];
        __syncthreads();
    }
    if (t == 0) g_bsums[blockIdx.x] = sh[0];
}

__global__ void k_scanB(int nb, int Lnext) {
    __shared__ int sh[256];
    int t = threadIdx.x;
    int v = (t < nb) ? g_bsums[t] : 0;
    sh[t] = v;
    __syncthreads();
    for (int d = 1; d < 256; d <<= 1) {
        int x = (t >= d) ? sh[t - d] : 0;
        __syncthreads();
        sh[t] += x;
        __syncthreads();
    }
    if (t < nb) g_bsums[t] = sh[t] - v;
    if (t == 255) g_n[Lnext] = sh[255];
}

__global__ void k_scanC(int* __restrict__ coarseGrid, int* __restrict__ linNext, int P) {
    __shared__ int sh[256];
    int t = threadIdx.x;
    int base = blockIdx.x * 1024;
    int f[4];
    int s = 0;
    #pragma unroll
    for (int j = 0; j < 4; j++) {
        int p = base + t * 4 + j;
        f[j] = (p < P) ? g_flags[p] : 0;
        s += f[j];
    }
    int v = s;
    sh[t] = v;
    __syncthreads();
    for (int d = 1; d < 256; d <<= 1) {
        int x = (t >= d) ? sh[t - d] : 0;
        __syncthreads();
        sh[t] += x;
        __syncthreads();
    }
    int off = g_bsums[blockIdx.x] + sh[t] - v;
    #pragma unroll
    for (int j = 0; j < 4; j++) {
        int p = base + t * 4 + j;
        if (p >= P) break;
        if (f[j]) {
            coarseGrid[p] = off;
            linNext[off] = p;
            off++;
        } else {
            coarseGrid[p] = -1;
        }
    }
}

__global__ void k_pool2(const float* __restrict__ feats, float* __restrict__ out,
                        __half* __restrict__ oh,
                        const int* __restrict__ fineGrid, const int* __restrict__ linNext,
                        const int* __restrict__ np, int S, int C, int CP) {
    int row = blockIdx.x;
    if (row >= *np) return;
    int Sc = S >> 1;
    int p = linNext[row];
    int pz = p / (Sc * Sc);
    int rem = p - pz * Sc * Sc;
    int py = rem / Sc;
    int px = rem - py * Sc;
    int c = threadIdx.x;
    if (c < C) {
        float m = -3.4e38f;
        #pragma unroll
        for (int a = 0; a < 2; a++)
            #pragma unroll
            for (int b = 0; b < 2; b++)
                #pragma unroll
                for (int d = 0; d < 2; d++) {
                    int l = ((2 * pz + a) * S + 2 * py + b) * S + 2 * px + d;
                    int r = fineGrid[l];
                    if (r >= 0) m = fmaxf(m, feats[(size_t)r * C + c]);
                }
        out[(size_t)row * C + c] = m;
        if (CP) oh[(size_t)row * CP + c] = __float2half_rn(m);
    } else if (CP && c < CP) {
        oh[(size_t)row * CP + c] = __float2half_rn(0.f);
    }
}

// ---------------------------------------------------------------------------

static inline int ceildiv(int a, int b) { return (a + b - 1) / b; }
static inline int pad64(int c) { return (c + 63) & ~63; }

static void launch_wconv(const __half* fin, const unsigned char* wb, float* outF,
                         __half* oh, int CP, const int* np, int CinP, int Cout,
                         int nBound, int gy) {
    int CoutS = Cout / gy;
    int NT = CoutS / 8;
    dim3 g(ceildiv(nBound, 128), gy), b(512);
    int smem = 2 * 16384 + 2 * 2 * CoutS * 128;
    switch (NT) {
        case 4:
            cudaFuncSetAttribute(k_wconv<4>, cudaFuncAttributeMaxDynamicSharedMemorySize, smem);
            k_wconv<4><<<g, b, smem>>>(fin, wb, outF, oh, CP, np, CinP, Cout);
            break;
        case 8:
            cudaFuncSetAttribute(k_wconv<8>, cudaFuncAttributeMaxDynamicSharedMemorySize, smem);
            k_wconv<8><<<g, b, smem>>>(fin, wb, outF, oh, CP, np, CinP, Cout);
            break;
        case 12:
            cudaFuncSetAttribute(k_wconv<12>, cudaFuncAttributeMaxDynamicSharedMemorySize, smem);
            k_wconv<12><<<g, b, smem>>>(fin, wb, outF, oh, CP, np, CinP, Cout);
            break;
        case 16:
            cudaFuncSetAttribute(k_wconv<16>, cudaFuncAttributeMaxDynamicSharedMemorySize, smem);
            k_wconv<16><<<g, b, smem>>>(fin, wb, outF, oh, CP, np, CinP, Cout);
            break;
    }
}

extern "C" void kernel_launch(void* const* d_in, const int* in_sizes, int n_in,
                              void* d_out, int out_size) {
    const float* feat_in = (const float*)d_in[0];
    const int*   coors   = (const int*)d_in[1];
    const float* w[14];
    for (int i = 0; i < 14; i++) w[i] = (const float*)d_in[3 + i];

    int n0 = in_sizes[0] / 3;

    float *fA, *fB;
    __half *t1, *t2;
    unsigned char* wblob;
    int *gA, *gB, *lA, *lB, *pn;
    cudaGetSymbolAddress((void**)&fA, g_featA);
    cudaGetSymbolAddress((void**)&fB, g_featB);
    cudaGetSymbolAddress((void**)&t1, g_fh1);
    cudaGetSymbolAddress((void**)&t2, g_fh2);
    cudaGetSymbolAddress((void**)&wblob, g_wblob);
    cudaGetSymbolAddress((void**)&gA, g_gridA);
    cudaGetSymbolAddress((void**)&gB, g_gridB);
    cudaGetSymbolAddress((void**)&lA, g_linA);
    cudaGetSymbolAddress((void**)&lB, g_linB);
    cudaGetSymbolAddress((void**)&pn, g_n);

    const int S[7]  = {128, 64, 32, 16, 8, 4, 2};
    int NB[7];
    NB[0] = n0;
    NB[1] = n0 < (64 * 64 * 64) ? n0 : (64 * 64 * 64);
    NB[2] = 32 * 32 * 32;
    NB[3] = 16 * 16 * 16;
    NB[4] = 8 * 8 * 8;
    NB[5] = 4 * 4 * 4;
    NB[6] = 2 * 2 * 2;
    const int Cin1[7]  = {3, 64, 96, 128, 160, 192, 224};
    const int Cout1[7] = {64, 96, 128, 160, 192, 224, 256};

    // MMA-path layers (0..7 == L0c1..L3c2); layer 0 handled by k_conv0
    const int LCin[8]  = {3, 64, 64, 96, 96, 128, 128, 160};
    const int LCinP[8] = {64, 64, 64, 128, 128, 128, 128, 192};
    const int LCout[8] = {64, 64, 96, 96, 128, 128, 160, 160};
    size_t woff[9];
    woff[0] = 0;
    for (int i = 0; i < 8; i++)
        woff[i + 1] = woff[i] + (size_t)27 * (LCinP[i] / 64) * 2 * LCout[i] * 128;

    // ---- weight blob (layers 1..7) + level-0 structure ----
    for (int i = 1; i < 8; i++) {
        int total = 27 * LCinP[i] * LCout[i];
        k_wcvt<<<ceildiv(total, 256), 256>>>(w[i], wblob + woff[i],
                                             LCin[i], LCinP[i], LCout[i]);
    }
    k_setn<<<1, 1>>>(n0);
    k_fill<<<ceildiv(GRID_CELLS, 256), 256>>>(gA, -1, GRID_CELLS);
    k_scatter0<<<ceildiv(n0, 256), 256>>>(coors, n0);

    int* linCur = lA;
    int* gridCur = gA;
    int* linNxt = lB;
    int* gridNxt = gB;

    // ---- MMA levels 0..3 ----
    for (int L = 0; L < 4; L++) {
        const int* np = pn + L;
        k_pairs<<<ceildiv(NB[L], 256), 256>>>(linCur, gridCur, np, S[L]);

        int li1 = 2 * L, li2 = 2 * L + 1;
        int gy = (L == 3) ? 5 : 1;
        if (L == 0) {
            k_conv0<<<ceildiv(NB[0], 4), 256>>>(feat_in, w[0], t2, np);
        } else {
            launch_wconv(t1, wblob + woff[li1], nullptr, t2, LCinP[li2],
                         np, LCinP[li1], LCout[li1], NB[L], gy);
        }
        launch_wconv(t2, wblob + woff[li2], fA, nullptr, 0,
                     np, LCinP[li2], LCout[li2], NB[L], gy);

        {
            int Sc = S[L] >> 1, P = Sc * Sc * Sc, nb = ceildiv(P, 1024);
            k_flags<<<ceildiv(P, 256), 256>>>(gridCur, S[L]);
            k_scanA<<<nb, 256>>>(P);
            k_scanB<<<1, 256>>>(nb, L + 1);
            k_scanC<<<nb, 256>>>(gridNxt, linNxt, P);
            int C = LCout[li2];
            int CP = (L < 3) ? pad64(C) : 0;
            int thr = CP ? CP : C;
            k_pool2<<<NB[L + 1], thr>>>(fA, fB, t1, gridCur, linNxt,
                                        pn + L + 1, S[L], C, CP);
        }
        int* t;
        t = linCur; linCur = linNxt; linNxt = t;
        t = gridCur; gridCur = gridNxt; gridNxt = t;
    }

    // ---- FFMA levels 4..6 (pool L3 output in fB) ----
    const float* cur = fB;
    for (int L = 4; L < 7; L++) {
        const int* np = pn + L;
        k_pairs<<<ceildiv(NB[L], 256), 256>>>(linCur, gridCur, np, S[L]);
        int ci1 = Cin1[L], co1 = Cout1[L];
        float* o1 = (cur == fB) ? fA : fB;
        {
            dim3 g(ceildiv(NB[L], 16), co1 / 32), b(256);
            k_conv_small<<<g, b>>>(cur, w[2 * L], o1, np, ci1, co1);
        }
        float* o2 = (L == 6) ? (float*)d_out : ((o1 == fA) ? fB : fA);
        {
            dim3 g(ceildiv(NB[L], 16), co1 / 32), b(256);
            k_conv_small<<<g, b>>>(o1, w[2 * L + 1], o2, np, co1, co1);
        }
        cur = o2;
        if (L < 6) {
            int Sc = S[L] >> 1, P = Sc * Sc * Sc, nb = ceildiv(P, 1024);
            k_flags<<<ceildiv(P, 256), 256>>>(gridCur, S[L]);
            k_scanA<<<nb, 256>>>(P);
            k_scanB<<<1, 256>>>(nb, L + 1);
            k_scanC<<<nb, 256>>>(gridNxt, linNxt, P);
            float* po = (cur == fA) ? fB : fA;
            k_pool2<<<NB[L + 1], co1>>>(cur, po, nullptr, gridCur, linNxt,
                                        pn + L + 1, S[L], co1, 0);
            cur = po;
            int* t;
            t = linCur; linCur = linNxt; linNxt = t;
            t = gridCur; gridCur = gridNxt; gridNxt = t;
        }
    }
}

// round 13
// speedup vs baseline: 1.5890x; 1.2121x over previous
#include <cuda_runtime.h>
#include <cuda_fp16.h>
#include <cstdint>

// ---------------------------------------------------------------------------
// Sparse submanifold 3D conv backbone, batch=1, 128^3 -> 2^3.
// L0 conv1 (Cin=3): neighbor-skipping scalar, writes fp16 feature table.
// L0c2..L3: mma.sync pure fp16 (A fp16, W fp16 single-limb), fp32 accumulate.
// Levels 4-6 (n <= 512): scalar FFMA path.
// ---------------------------------------------------------------------------

#define NMAX 100000
#define GRID_CELLS (1 << 21)
#define FLAGS_MAX (1 << 18)

__device__ int   g_n[8];
__device__ int   g_linA[NMAX];
__device__ int   g_linB[NMAX];
__device__ int   g_gridA[GRID_CELLS];
__device__ int   g_gridB[GRID_CELLS];
__device__ int   g_pairs[27 * NMAX];
__device__ int   g_flags[FLAGS_MAX];
__device__ int   g_bsums[256];
__device__ __align__(1024) float g_featA[10000000];
__device__ __align__(1024) float g_featB[10000000];
// fp16 feature tables: t1 = conv1 input, t2 = conv2 input
__device__ __align__(1024) __half g_fh1[12000000];
__device__ __align__(1024) __half g_fh2[12000000];
// pre-swizzled, transposed fp16 weight blob (layers 1..7)
__device__ __align__(1024) unsigned char g_wblob[16 * 1024 * 1024];

// ---------------------------------------------------------------------------

__device__ __forceinline__ void cp_async16(uint32_t dst, const void* src, int srcBytes) {
    asm volatile("cp.async.cg.shared.global [%0], [%1], 16, %2;\n"
                 :: "r"(dst), "l"(src), "r"(srcBytes));
}
__device__ __forceinline__ void cp_commit() {
    asm volatile("cp.async.commit_group;\n");
}
__device__ __forceinline__ uint32_t smem_u32(const void* p) {
    uint32_t a;
    asm("{ .reg .u64 t; cvta.to.shared.u64 t, %1; cvt.u32.u64 %0, t; }" : "=r"(a) : "l"(p));
    return a;
}
__device__ __forceinline__ void ldsm4(uint32_t* r, uint32_t addr) {
    asm volatile("ldmatrix.sync.aligned.m8n8.x4.shared.b16 {%0,%1,%2,%3}, [%4];"
                 : "=r"(r[0]), "=r"(r[1]), "=r"(r[2]), "=r"(r[3]) : "r"(addr));
}
__device__ __forceinline__ void ldsm2(uint32_t* r, uint32_t addr) {
    asm volatile("ldmatrix.sync.aligned.m8n8.x2.shared.b16 {%0,%1}, [%2];"
                 : "=r"(r[0]), "=r"(r[1]) : "r"(addr));
}
__device__ __forceinline__ void mma16816(float* d, const uint32_t* a, const uint32_t* b) {
    asm volatile("mma.sync.aligned.m16n8k16.row.col.f32.f16.f16.f32 "
                 "{%0,%1,%2,%3}, {%4,%5,%6,%7}, {%8,%9}, {%0,%1,%2,%3};"
                 : "+f"(d[0]), "+f"(d[1]), "+f"(d[2]), "+f"(d[3])
                 : "r"(a[0]), "r"(a[1]), "r"(a[2]), "r"(a[3]), "r"(b[0]), "r"(b[1]));
}

// ---------------------------------------------------------------------------

__global__ void k_setn(int n0) { g_n[0] = n0; }

__global__ void k_fill(int* g, int v, int P) {
    int i = blockIdx.x * blockDim.x + threadIdx.x;
    if (i < P) g[i] = v;
}

__global__ void k_scatter0(const int* __restrict__ coors, int n0) {
    int i = blockIdx.x * blockDim.x + threadIdx.x;
    if (i >= n0) return;
    int z = coors[i * 4 + 1];
    int y = coors[i * 4 + 2];
    int x = coors[i * 4 + 3];
    int l = (z * 128 + y) * 128 + x;
    g_linA[i] = l;
    g_gridA[l] = i;
}

__global__ void k_pairs(const int* __restrict__ lin, const int* __restrict__ grid,
                        const int* __restrict__ np, int S) {
    int n = *np;
    int i = blockIdx.x * blockDim.x + threadIdx.x;
    if (i >= n) return;
    int l = lin[i];
    int z = l / (S * S);
    int rem = l - z * S * S;
    int y = rem / S;
    int x = rem - y * S;
    int k = 0;
    #pragma unroll
    for (int dz = -1; dz <= 1; dz++)
        #pragma unroll
        for (int dy = -1; dy <= 1; dy++)
            #pragma unroll
            for (int dx = -1; dx <= 1; dx++) {
                int zz = z + dz, yy = y + dy, xx = x + dx;
                int v = -1;
                if (zz >= 0 && zz < S && yy >= 0 && yy < S && xx >= 0 && xx < S)
                    v = grid[(zz * S + yy) * S + xx];
                g_pairs[k * NMAX + i] = v;
                k++;
            }
}

// Weight blob: W[27,Cin,Cout] fp32 -> per-stage SW128 images of W^T
// [Cout rows x 64 cols] fp16 single-limb. Stage = (k, ci-chunk).
__global__ void k_wcvt(const float* __restrict__ W, unsigned char* __restrict__ blob,
                       int Cin, int CinP, int Cout) {
    int total = 27 * CinP * Cout;
    int idx = blockIdx.x * 256 + threadIdx.x;
    if (idx >= total) return;
    int ci = idx % CinP;
    int t = idx / CinP;
    int co = t % Cout;
    int k = t / Cout;
    float v = (ci < Cin) ? W[((size_t)k * Cin + ci) * Cout + co] : 0.f;
    __half h = __float2half_rn(v);
    int ch = ci >> 6, cic = ci & 63;
    int sw = (((cic >> 3) ^ (co & 7)) << 4) + (cic & 7) * 2;
    int NCH = CinP >> 6;
    size_t stageBase = (size_t)(k * NCH + ch) * (Cout * 128);
    *(__half*)(blob + stageBase + (size_t)co * 128 + sw) = h;
}

// ---------------------------------------------------------------------------
// Fused L0 conv1: Cin=3, Cout=64, writes fp16 table (CP=64), skips missing.
// ---------------------------------------------------------------------------
__global__ __launch_bounds__(256) void k_conv0(const float* __restrict__ feats,
                                               const float* __restrict__ W,
                                               __half* __restrict__ out,
                                               const int* __restrict__ np) {
    __shared__ float Ws[27 * 3 * 64];
    int n = *np;
    int tid = threadIdx.x;
    for (int e = tid; e < 27 * 3 * 64; e += 256) Ws[e] = W[e];
    __syncthreads();
    int r = blockIdx.x * 4 + (tid >> 6);
    int lane = tid & 63;
    if (r >= n) return;
    float acc = 0.f;
    #pragma unroll 1
    for (int k = 0; k < 27; k++) {
        int id = g_pairs[k * NMAX + r];
        if (id >= 0) {
            float f0 = feats[id * 3 + 0];
            float f1 = feats[id * 3 + 1];
            float f2 = feats[id * 3 + 2];
            const float* wk = Ws + k * 192;
            acc += f0 * wk[lane] + f1 * wk[64 + lane] + f2 * wk[128 + lane];
        }
    }
    out[(size_t)r * 64 + lane] = __float2half_rn(acc);
}

// ---------------------------------------------------------------------------
// mma.sync conv: 128-row tile x CoutS col slice, pure fp16, fp32 accumulate.
// 512 threads = 16 warps = 4 row-groups x 4 col-quarters.
// 2-stage cp.async pipeline. A: single fp16 table, W: single fp16 limb.
// ---------------------------------------------------------------------------
template <int NT>   // NT = CoutS/8, divisible by 4
__global__ __launch_bounds__(512) void k_wconv(
    const __half* __restrict__ fin,
    const unsigned char* __restrict__ wblob,
    float* __restrict__ outF,
    __half* __restrict__ outH, int CP,
    const int* __restrict__ np, int CinP, int CoutF)
{
    const int NT4 = NT / 4;
    const int CoutS = NT * 8;
    const int WstageS = CoutS * 128;
    int n = *np;
    int rowBase = blockIdx.x * 128;
    if (rowBase >= n) return;
    int colBase = blockIdx.y * CoutS;

    extern __shared__ __align__(1024) unsigned char sm[];
    const uint32_t Asm = smem_u32(sm);        // 2 stages x 16KB
    const uint32_t Wsm = Asm + 2 * 16384;

    int tid = threadIdx.x;
    int wid = tid >> 5;
    int lane = tid & 31;

    const int NCH = CinP >> 6;
    const int S = 27 * NCH;
    const int WstageF = CoutF * 128;

    // A-gather: 4 threads per row, each loads 2 x 16B chunks
    int am = tid >> 2;        // 0..127 row
    int q = tid & 3;          // chunk group
    int r_g = rowBase + am;
    int curK = -1, curId = -1;

    float acc[2][NT4][4];
    #pragma unroll
    for (int mt = 0; mt < 2; mt++)
        #pragma unroll
        for (int j = 0; j < NT4; j++)
            #pragma unroll
            for (int p = 0; p < 4; p++) acc[mt][j][p] = 0.f;

    auto load = [&](int buf, int s) {
        int k = s / NCH;
        int ch = s - k * NCH;
        if (k != curK) {
            curK = k;
            curId = (r_g < n) ? g_pairs[k * NMAX + r_g] : -1;
        }
        {
            const unsigned char* src =
                (const unsigned char*)(fin + (size_t)(curId < 0 ? 0 : curId) * CinP + ch * 64);
            uint32_t dst = Asm + buf * 16384 + am * 128;
            int m7 = (am & 7) << 4;
            int sz = (curId >= 0) ? 16 : 0;
            #pragma unroll
            for (int c = q * 2; c < q * 2 + 2; c++)
                cp_async16(dst + ((c << 4) ^ m7), src + c * 16, sz);
        }
        {
            const unsigned char* src = wblob + (size_t)s * WstageF
                                     + (size_t)colBase * 128;
            const int hc = (CoutS * 128) >> 4;
            uint32_t dst = Wsm + buf * WstageS;
            for (int e = tid; e < hc; e += 512)
                cp_async16(dst + e * 16, src + e * 16, 16);
        }
        cp_commit();
    };

    int rw = wid & 3;
    int cw = wid >> 2;
    int arow0 = rw * 32 + (lane & 15);
    int ac16 = (lane >> 4) & 1;
    int brow_l = lane & 7;
    int bc16 = (lane >> 3) & 1;

    load(0, 0);
    for (int s = 0; s < S; s++) {
        int b = s & 1;
        if (s + 1 < S) {
            load(b ^ 1, s + 1);
            asm volatile("cp.async.wait_group 1;\n");
        } else {
            asm volatile("cp.async.wait_group 0;\n");
        }
        __syncthreads();

        uint32_t AhB = Asm + b * 16384;
        uint32_t WhB = Wsm + b * WstageS;

        #pragma unroll
        for (int chunk = 0; chunk < 4; chunk++) {
            uint32_t ah[2][4];
            #pragma unroll
            for (int mt = 0; mt < 2; mt++) {
                uint32_t off = (uint32_t)(arow0 + mt * 16) * 128 + chunk * 32 + ac16 * 16;
                off ^= (off >> 3) & 0x70;
                ldsm4(ah[mt], AhB + off);
            }
            #pragma unroll
            for (int j = 0; j < NT4; j++) {
                uint32_t off = (uint32_t)(cw * (NT4 * 8) + j * 8 + brow_l) * 128
                             + chunk * 32 + bc16 * 16;
                off ^= (off >> 3) & 0x70;
                uint32_t bh[2];
                ldsm2(bh, WhB + off);
                #pragma unroll
                for (int mt = 0; mt < 2; mt++)
                    mma16816(acc[mt][j], ah[mt], bh);
            }
        }
        __syncthreads();
    }

    int grp = lane >> 2, tg = lane & 3;
    #pragma unroll
    for (int mt = 0; mt < 2; mt++) {
        int r0 = rowBase + rw * 32 + mt * 16 + grp;
        #pragma unroll
        for (int half = 0; half < 2; half++) {
            int r = r0 + half * 8;
            if (r >= n) continue;
            #pragma unroll
            for (int j = 0; j < NT4; j++) {
                float d0 = acc[mt][j][half * 2 + 0];
                float d1 = acc[mt][j][half * 2 + 1];
                int c = colBase + cw * (NT4 * 8) + j * 8 + tg * 2;
                if (outF) {
                    float2 v; v.x = d0; v.y = d1;
                    *(float2*)(outF + (size_t)r * CoutF + c) = v;
                }
                if (outH) {
                    __half h0 = __float2half_rn(d0);
                    __half h1 = __float2half_rn(d1);
                    uint32_t hp = ((uint32_t)(*(unsigned short*)&h1) << 16)
                                | (uint32_t)(*(unsigned short*)&h0);
                    *(uint32_t*)(outH + (size_t)r * CP + c) = hp;
                }
            }
            if (outH && blockIdx.y == 0 && cw == 0) {
                for (int c = CoutF + tg * 2; c < CP; c += 8)
                    *(uint32_t*)(outH + (size_t)r * CP + c) = 0u;
            }
        }
    }
}

// ---------------------------------------------------------------------------
// Small-level scalar conv (n <= 512): 16 rows x 32 cols per block.
// ---------------------------------------------------------------------------
__global__ __launch_bounds__(256) void k_conv_small(const float* __restrict__ feats,
                                                    const float* __restrict__ W,
                                                    float* __restrict__ out,
                                                    const int* __restrict__ np,
                                                    int Cin, int Cout) {
    int n = *np;
    int rowBase = blockIdx.x * 16;
    if (rowBase >= n) return;
    int colBase = blockIdx.y * 32;

    __shared__ float As[16][33];
    __shared__ float Ws[32][33];

    int tid = threadIdx.x;
    int tm = tid >> 5;
    int tn = tid & 31;

    float acc0 = 0.f, acc1 = 0.f;

    for (int k = 0; k < 27; k++) {
        for (int c0 = 0; c0 < Cin; c0 += 32) {
            __syncthreads();
            {
                int e = tid;
                #pragma unroll
                for (int j = 0; j < 2; j++, e += 256) {
                    int m = e >> 5, c = e & 31;
                    int r = rowBase + m;
                    int id = (r < n) ? g_pairs[k * NMAX + r] : -1;
                    As[m][c] = (id >= 0) ? feats[(size_t)id * Cin + c0 + c] : 0.f;
                }
            }
            {
                const float* Wk = W + ((size_t)k * Cin + c0) * Cout + colBase;
                int e = tid;
                #pragma unroll
                for (int j = 0; j < 4; j++, e += 256) {
                    int kk = e >> 5, c = e & 31;
                    Ws[kk][c] = Wk[(size_t)kk * Cout + c];
                }
            }
            __syncthreads();
            #pragma unroll 8
            for (int kk = 0; kk < 32; kk++) {
                float w = Ws[kk][tn];
                acc0 += As[tm * 2][kk] * w;
                acc1 += As[tm * 2 + 1][kk] * w;
            }
        }
    }

    int r0 = rowBase + tm * 2;
    if (r0 < n)     out[(size_t)r0 * Cout + colBase + tn] = acc0;
    if (r0 + 1 < n) out[(size_t)(r0 + 1) * Cout + colBase + tn] = acc1;
}

// ---------------------------------------------------------------------------
// Pool structure kernels + pool with optional fp16 output table
// ---------------------------------------------------------------------------
__global__ void k_flags(const int* __restrict__ fineGrid, int S) {
    int Sc = S >> 1;
    int P = Sc * Sc * Sc;
    int p = blockIdx.x * blockDim.x + threadIdx.x;
    if (p >= P) return;
    int pz = p / (Sc * Sc);
    int rem = p - pz * Sc * Sc;
    int py = rem / Sc;
    int px = rem - py * Sc;
    int occ = 0;
    #pragma unroll
    for (int a = 0; a < 2; a++)
        #pragma unroll
        for (int b = 0; b < 2; b++)
            #pragma unroll
            for (int c = 0; c < 2; c++) {
                int l = ((2 * pz + a) * S + 2 * py + b) * S + 2 * px + c;
                if (fineGrid[l] >= 0) occ = 1;
            }
    g_flags[p] = occ;
}

__global__ void k_scanA(int P) {
    __shared__ int sh[256];
    int t = threadIdx.x;
    int base = blockIdx.x * 1024;
    int s = 0;
    #pragma unroll
    for (int j = 0; j < 4; j++) {
        int p = base + t * 4 + j;
        if (p < P) s += g_flags[p];
    }
    sh[t] = s;
    __syncthreads();
    for (int d = 128; d > 0; d >>= 1) {
        if (t < d) sh[t] += sh[t + d];
        __syncthreads();
    }
    if (t == 0) g_bsums[blockIdx.x] = sh[0];
}

__global__ void k_scanB(int nb, int Lnext) {
    __shared__ int sh[256];
    int t = threadIdx.x;
    int v = (t < nb) ? g_bsums[t] : 0;
    sh[t] = v;
    __syncthreads();
    for (int d = 1; d < 256; d <<= 1) {
        int x = (t >= d) ? sh[t - d] : 0;
        __syncthreads();
        sh[t] += x;
        __syncthreads();
    }
    if (t < nb) g_bsums[t] = sh[t] - v;
    if (t == 255) g_n[Lnext] = sh[255];
}

__global__ void k_scanC(int* __restrict__ coarseGrid, int* __restrict__ linNext, int P) {
    __shared__ int sh[256];
    int t = threadIdx.x;
    int base = blockIdx.x * 1024;
    int f[4];
    int s = 0;
    #pragma unroll
    for (int j = 0; j < 4; j++) {
        int p = base + t * 4 + j;
        f[j] = (p < P) ? g_flags[p] : 0;
        s += f[j];
    }
    int v = s;
    sh[t] = v;
    __syncthreads();
    for (int d = 1; d < 256; d <<= 1) {
        int x = (t >= d) ? sh[t - d] : 0;
        __syncthreads();
        sh[t] += x;
        __syncthreads();
    }
    int off = g_bsums[blockIdx.x] + sh[t] - v;
    #pragma unroll
    for (int j = 0; j < 4; j++) {
        int p = base + t * 4 + j;
        if (p >= P) break;
        if (f[j]) {
            coarseGrid[p] = off;
            linNext[off] = p;
            off++;
        } else {
            coarseGrid[p] = -1;
        }
    }
}

__global__ void k_pool2(const float* __restrict__ feats, float* __restrict__ out,
                        __half* __restrict__ oh,
                        const int* __restrict__ fineGrid, const int* __restrict__ linNext,
                        const int* __restrict__ np, int S, int C, int CP) {
    int row = blockIdx.x;
    if (row >= *np) return;
    int Sc = S >> 1;
    int p = linNext[row];
    int pz = p / (Sc * Sc);
    int rem = p - pz * Sc * Sc;
    int py = rem / Sc;
    int px = rem - py * Sc;
    int c = threadIdx.x;
    if (c < C) {
        float m = -3.4e38f;
        #pragma unroll
        for (int a = 0; a < 2; a++)
            #pragma unroll
            for (int b = 0; b < 2; b++)
                #pragma unroll
                for (int d = 0; d < 2; d++) {
                    int l = ((2 * pz + a) * S + 2 * py + b) * S + 2 * px + d;
                    int r = fineGrid[l];
                    if (r >= 0) m = fmaxf(m, feats[(size_t)r * C + c]);
                }
        out[(size_t)row * C + c] = m;
        if (CP) oh[(size_t)row * CP + c] = __float2half_rn(m);
    } else if (CP && c < CP) {
        oh[(size_t)row * CP + c] = __float2half_rn(0.f);
    }
}

// ---------------------------------------------------------------------------

static inline int ceildiv(int a, int b) { return (a + b - 1) / b; }
static inline int pad64(int c) { return (c + 63) & ~63; }

static void launch_wconv(const __half* fin, const unsigned char* wb, float* outF,
                         __half* oh, int CP, const int* np, int CinP, int Cout,
                         int nBound, int gy) {
    int CoutS = Cout / gy;
    int NT = CoutS / 8;
    dim3 g(ceildiv(nBound, 128), gy), b(512);
    int smem = 2 * 16384 + 2 * CoutS * 128;
    switch (NT) {
        case 4:
            cudaFuncSetAttribute(k_wconv<4>, cudaFuncAttributeMaxDynamicSharedMemorySize, smem);
            k_wconv<4><<<g, b, smem>>>(fin, wb, outF, oh, CP, np, CinP, Cout);
            break;
        case 8:
            cudaFuncSetAttribute(k_wconv<8>, cudaFuncAttributeMaxDynamicSharedMemorySize, smem);
            k_wconv<8><<<g, b, smem>>>(fin, wb, outF, oh, CP, np, CinP, Cout);
            break;
        case 12:
            cudaFuncSetAttribute(k_wconv<12>, cudaFuncAttributeMaxDynamicSharedMemorySize, smem);
            k_wconv<12><<<g, b, smem>>>(fin, wb, outF, oh, CP, np, CinP, Cout);
            break;
        case 16:
            cudaFuncSetAttribute(k_wconv<16>, cudaFuncAttributeMaxDynamicSharedMemorySize, smem);
            k_wconv<16><<<g, b, smem>>>(fin, wb, outF, oh, CP, np, CinP, Cout);
            break;
    }
}

extern "C" void kernel_launch(void* const* d_in, const int* in_sizes, int n_in,
                              void* d_out, int out_size) {
    const float* feat_in = (const float*)d_in[0];
    const int*   coors   = (const int*)d_in[1];
    const float* w[14];
    for (int i = 0; i < 14; i++) w[i] = (const float*)d_in[3 + i];

    int n0 = in_sizes[0] / 3;

    float *fA, *fB;
    __half *t1, *t2;
    unsigned char* wblob;
    int *gA, *gB, *lA, *lB, *pn;
    cudaGetSymbolAddress((void**)&fA, g_featA);
    cudaGetSymbolAddress((void**)&fB, g_featB);
    cudaGetSymbolAddress((void**)&t1, g_fh1);
    cudaGetSymbolAddress((void**)&t2, g_fh2);
    cudaGetSymbolAddress((void**)&wblob, g_wblob);
    cudaGetSymbolAddress((void**)&gA, g_gridA);
    cudaGetSymbolAddress((void**)&gB, g_gridB);
    cudaGetSymbolAddress((void**)&lA, g_linA);
    cudaGetSymbolAddress((void**)&lB, g_linB);
    cudaGetSymbolAddress((void**)&pn, g_n);

    const int S[7]  = {128, 64, 32, 16, 8, 4, 2};
    int NB[7];
    NB[0] = n0;
    NB[1] = n0 < (64 * 64 * 64) ? n0 : (64 * 64 * 64);
    NB[2] = 32 * 32 * 32;
    NB[3] = 16 * 16 * 16;
    NB[4] = 8 * 8 * 8;
    NB[5] = 4 * 4 * 4;
    NB[6] = 2 * 2 * 2;
    const int Cin1[7]  = {3, 64, 96, 128, 160, 192, 224};
    const int Cout1[7] = {64, 96, 128, 160, 192, 224, 256};

    // MMA-path layers (0..7 == L0c1..L3c2); layer 0 handled by k_conv0
    const int LCin[8]  = {3, 64, 64, 96, 96, 128, 128, 160};
    const int LCinP[8] = {64, 64, 64, 128, 128, 128, 128, 192};
    const int LCout[8] = {64, 64, 96, 96, 128, 128, 160, 160};
    size_t woff[9];
    woff[0] = 0;
    for (int i = 0; i < 8; i++)
        woff[i + 1] = woff[i] + (size_t)27 * (LCinP[i] / 64) * LCout[i] * 128;

    // ---- weight blob (layers 1..7) + level-0 structure ----
    for (int i = 1; i < 8; i++) {
        int total = 27 * LCinP[i] * LCout[i];
        k_wcvt<<<ceildiv(total, 256), 256>>>(w[i], wblob + woff[i],
                                             LCin[i], LCinP[i], LCout[i]);
    }
    k_setn<<<1, 1>>>(n0);
    k_fill<<<ceildiv(GRID_CELLS, 256), 256>>>(gA, -1, GRID_CELLS);
    k_scatter0<<<ceildiv(n0, 256), 256>>>(coors, n0);

    int* linCur = lA;
    int* gridCur = gA;
    int* linNxt = lB;
    int* gridNxt = gB;

    // ---- MMA levels 0..3 ----
    for (int L = 0; L < 4; L++) {
        const int* np = pn + L;
        k_pairs<<<ceildiv(NB[L], 256), 256>>>(linCur, gridCur, np, S[L]);

        int li1 = 2 * L, li2 = 2 * L + 1;
        int gy = (L == 3) ? 5 : 1;
        if (L == 0) {
            k_conv0<<<ceildiv(NB[0], 4), 256>>>(feat_in, w[0], t2, np);
        } else {
            launch_wconv(t1, wblob + woff[li1], nullptr, t2, LCinP[li2],
                         np, LCinP[li1], LCout[li1], NB[L], gy);
        }
        launch_wconv(t2, wblob + woff[li2], fA, nullptr, 0,
                     np, LCinP[li2], LCout[li2], NB[L], gy);

        {
            int Sc = S[L] >> 1, P = Sc * Sc * Sc, nb = ceildiv(P, 1024);
            k_flags<<<ceildiv(P, 256), 256>>>(gridCur, S[L]);
            k_scanA<<<nb, 256>>>(P);
            k_scanB<<<1, 256>>>(nb, L + 1);
            k_scanC<<<nb, 256>>>(gridNxt, linNxt, P);
            int C = LCout[li2];
            int CP = (L < 3) ? pad64(C) : 0;
            int thr = CP ? CP : C;
            k_pool2<<<NB[L + 1], thr>>>(fA, fB, t1, gridCur, linNxt,
                                        pn + L + 1, S[L], C, CP);
        }
        int* t;
        t = linCur; linCur = linNxt; linNxt = t;
        t = gridCur; gridCur = gridNxt; gridNxt = t;
    }

    // ---- FFMA levels 4..6 (pool L3 output in fB) ----
    const float* cur = fB;
    for (int L = 4; L < 7; L++) {
        const int* np = pn + L;
        k_pairs<<<ceildiv(NB[L], 256), 256>>>(linCur, gridCur, np, S[L]);
        int ci1 = Cin1[L], co1 = Cout1[L];
        float* o1 = (cur == fB) ? fA : fB;
        {
            dim3 g(ceildiv(NB[L], 16), co1 / 32), b(256);
            k_conv_small<<<g, b>>>(cur, w[2 * L], o1, np, ci1, co1);
        }
        float* o2 = (L == 6) ? (float*)d_out : ((o1 == fA) ? fB : fA);
        {
            dim3 g(ceildiv(NB[L], 16), co1 / 32), b(256);
            k_conv_small<<<g, b>>>(o1, w[2 * L + 1], o2, np, co1, co1);
        }
        cur = o2;
        if (L < 6) {
            int Sc = S[L] >> 1, P = Sc * Sc * Sc, nb = ceildiv(P, 1024);
            k_flags<<<ceildiv(P, 256), 256>>>(gridCur, S[L]);
            k_scanA<<<nb, 256>>>(P);
            k_scanB<<<1, 256>>>(nb, L + 1);
            k_scanC<<<nb, 256>>>(gridNxt, linNxt, P);
            float* po = (cur == fA) ? fB : fA;
            k_pool2<<<NB[L + 1], co1>>>(cur, po, nullptr, gridCur, linNxt,
                                        pn + L + 1, S[L], co1, 0);
            cur = po;
            int* t;
            t = linCur; linCur = linNxt; linNxt = t;
            t = gridCur; gridCur = gridNxt; gridNxt = t;
        }
    }
}